// round 13
// baseline (speedup 1.0000x reference)
#include <cuda_runtime.h>
#include <cuda_fp16.h>
#include <math.h>
#include <stdint.h>

// ---------------- problem constants ----------------
#define LSEQ   2048
#define DMODEL 1024
#define DINNER 2048
#define DSTATE 16
#define DTRANK 64
#define XDBL   96
#define NEXP   8
#define HIDDEN 4096
#define NPAIR  4096
#define SPLITK 8

// ---------------- fp32 scratch ----------------
__device__ float g_xn   [LSEQ * DMODEL];
__device__ float g_xr   [LSEQ * 2 * DINNER];
__device__ float g_u    [LSEQ * DINNER];
__device__ float g_xdbl [LSEQ * XDBL];
__device__ float g_xp   [SPLITK * LSEQ * XDBL];
__device__ float g_delta[LSEQ * DINNER];
__device__ float g_xm2  [LSEQ * DMODEL];
__device__ float g_xm2n [LSEQ * DMODEL];
__device__ float g_y2   [(size_t)NPAIR * DMODEL];
__device__ int   g_top_e[LSEQ * 2];
__device__ float g_top_v[LSEQ * 2];
__device__ int   g_off[NEXP + 1];
__device__ int   g_ptok[NPAIR];
__device__ float g_pw  [NPAIR];
__device__ int   g_tok_pair[LSEQ * 2];

// ---------------- fp16 scratch ----------------
__device__ __align__(16) __half h_xn [LSEQ * DMODEL];
__device__ __align__(16) __half h_xd [LSEQ * XDBL];
__device__ __align__(16) __half h_y  [LSEQ * DINNER];
__device__ __align__(16) __half h_x2 [LSEQ * DMODEL];
__device__ __align__(16) __half h_h  [(size_t)NPAIR * HIDDEN];

// ---------------- helpers ----------------
__device__ __forceinline__ void cpa16(uint32_t dst, const void* src)
{
    asm volatile("cp.async.cg.shared.global [%0], [%1], 16;" :: "r"(dst), "l"(src));
}

__device__ __forceinline__ void ldsm4(uint32_t* r, uint32_t a)
{
    asm volatile("ldmatrix.sync.aligned.m8n8.x4.shared.b16 {%0,%1,%2,%3}, [%4];"
                 : "=r"(r[0]), "=r"(r[1]), "=r"(r[2]), "=r"(r[3]) : "r"(a));
}

__device__ __forceinline__ void hmma(float* d, const uint32_t* a, const uint32_t* b)
{
    asm volatile(
        "mma.sync.aligned.m16n8k16.row.col.f32.f16.f16.f32 "
        "{%0,%1,%2,%3},{%4,%5,%6,%7},{%8,%9},{%0,%1,%2,%3};\n"
        : "+f"(d[0]), "+f"(d[1]), "+f"(d[2]), "+f"(d[3])
        : "r"(a[0]), "r"(a[1]), "r"(a[2]), "r"(a[3]), "r"(b[0]), "r"(b[1]));
}

__device__ __forceinline__ uint2 cvt4(float4 v)
{
    __half2 h01 = __halves2half2(__float2half_rn(v.x), __float2half_rn(v.y));
    __half2 h23 = __halves2half2(__float2half_rn(v.z), __float2half_rn(v.w));
    return make_uint2(*(uint32_t*)&h01, *(uint32_t*)&h23);
}

__device__ __forceinline__ uint4 cvt8(float4 a, float4 b)
{
    uint2 lo = cvt4(a), hi = cvt4(b);
    return make_uint4(lo.x, lo.y, hi.x, hi.y);
}

// ---------------- fp16 tensor GEMM: C = epi(A @ W^T) ----------------
// A: (M,K) fp16 row-major stride lda. W: (N,K) fp32, converted in-kernel.
// CTA tile 128x128, k-stage 32, 3-stage cp.async pipeline (1 sync/iter).
// EPI: 0 store fp32, 1 gelu->fp16, 2 +addsrc fp32, 3 softplus(+bias) fp32
// MODE: 0 plain, 1 gather A rows via ptok + per-expert W, 2 contiguous expert rows
#define NSTG 3
#define STG_B 16384
template<int EPI, int MODE>
__global__ void __launch_bounds__(256, 2) hgemm(
    const __half* __restrict__ Aq, int lda,
    const float* __restrict__ Wf, int K,
    float* __restrict__ C, int ldc, int M, int N,
    const float* __restrict__ bias, const float* __restrict__ addsrc, int ldadd,
    const int* __restrict__ off, const int* __restrict__ ptok,
    __half* __restrict__ Ch)
{
    extern __shared__ __align__(16) uint8_t smem[];
    int base = 0, rows = M;
    const float* WF = Wf;
    if (MODE != 0) {
        int e = blockIdx.z;
        base = off[e];
        rows = off[e + 1] - base;
        WF += (size_t)e * (size_t)N * K;
    }
    int m0 = blockIdx.x * 128;
    if (m0 >= rows) return;
    int n0 = blockIdx.y * 128;

    int tid = threadIdx.x;
    int wid = tid >> 5, lane = tid & 31;
    int lr = lane >> 2, lc = lane & 3;
    int warp_m = wid >> 2, warp_n = wid & 3;

    // ---- global load mapping ----
    int qg = tid & 3;
    int ar = tid >> 2;                 // 0..63
    int rA0 = m0 + ar, rA1 = rA0 + 64;
    int c0 = rA0 < rows ? rA0 : rows - 1;
    int c1 = rA1 < rows ? rA1 : rows - 1;
    int gA0, gA1;
    if (MODE == 1)      { gA0 = ptok[base + c0]; gA1 = ptok[base + c1]; }
    else if (MODE == 2) { gA0 = base + c0;       gA1 = base + c1; }
    else                { gA0 = c0;              gA1 = c1; }

    const __half* pA0 = Aq + (size_t)gA0 * lda + qg * 8;
    const __half* pA1 = Aq + (size_t)gA1 * lda + qg * 8;
    const float*  pB0f = WF + (size_t)(n0 + ar) * K + qg * 8;
    const float*  pB1f = WF + (size_t)(n0 + ar + 64) * K + qg * 8;

    uint32_t sb0 = (uint32_t)__cvta_generic_to_shared(smem);
    int dst0 = ar * 64 + ((qg ^ ((ar >> 1) & 3)) << 4);
    int dst1 = dst0 + 4096;

    // ---- per-lane ldmatrix addresses ----
    int rA = warp_m * 64 + (lane & 15);
    int swzA = (rA >> 1) & 3;
    int aoff0 = rA * 64 + ((((lane >> 4)) ^ swzA) << 4);
    int aoff1 = rA * 64 + (((2 + (lane >> 4)) ^ swzA) << 4);
    int rB = warp_n * 32 + (lane & 7) + ((lane >> 4) << 3);
    int swzB = (rB >> 1) & 3;
    int boff0 = rB * 64 + ((((lane >> 3) & 1) ^ swzB) << 4);
    int boff1 = rB * 64 + (((2 + ((lane >> 3) & 1)) ^ swzB) << 4);

    float acc[4][4][4];
    #pragma unroll
    for (int i = 0; i < 4; i++)
        #pragma unroll
        for (int j = 0; j < 4; j++)
            #pragma unroll
            for (int r = 0; r < 4; r++) acc[i][j][r] = 0.f;

    int nt = K >> 5;
    float4 br[4];   // staged fp32 B
    // prologue: stages 0 and 1
    {
        br[0] = __ldg((const float4*)pB0f);
        br[1] = __ldg((const float4*)(pB0f + 4));
        br[2] = __ldg((const float4*)pB1f);
        br[3] = __ldg((const float4*)(pB1f + 4));
        *(uint4*)(smem + 8192 + dst0) = cvt8(br[0], br[1]);
        *(uint4*)(smem + 8192 + dst1) = cvt8(br[2], br[3]);
        cpa16(sb0 + dst0, pA0);
        cpa16(sb0 + dst1, pA1);
        asm volatile("cp.async.commit_group;");
        if (nt > 1) {
            br[0] = __ldg((const float4*)(pB0f + 32));
            br[1] = __ldg((const float4*)(pB0f + 36));
            br[2] = __ldg((const float4*)(pB1f + 32));
            br[3] = __ldg((const float4*)(pB1f + 36));
            uint32_t s = sb0 + STG_B;
            cpa16(s + dst0, pA0 + 32);
            cpa16(s + dst1, pA1 + 32);
        }
        asm volatile("cp.async.commit_group;");
    }
    int buf = 0;
    for (int t = 0; t < nt; t++) {
        asm volatile("cp.async.wait_group 1;");
        __syncthreads();
        // STS B(t+1) (regs loaded last iter / prologue) into buf (t+1)%3
        if (t + 1 < nt) {
            int nb1 = buf + 1; if (nb1 >= NSTG) nb1 -= NSTG;
            *(uint4*)(smem + nb1 * STG_B + 8192 + dst0) = cvt8(br[0], br[1]);
            *(uint4*)(smem + nb1 * STG_B + 8192 + dst1) = cvt8(br[2], br[3]);
        }
        if (t + 2 < nt) {
            int kc = (t + 2) << 5;
            br[0] = __ldg((const float4*)(pB0f + kc));
            br[1] = __ldg((const float4*)(pB0f + kc + 4));
            br[2] = __ldg((const float4*)(pB1f + kc));
            br[3] = __ldg((const float4*)(pB1f + kc + 4));
            int nb = buf + 2; if (nb >= NSTG) nb -= NSTG;
            uint32_t s = sb0 + nb * STG_B;
            cpa16(s + dst0, pA0 + kc);
            cpa16(s + dst1, pA1 + kc);
        }
        asm volatile("cp.async.commit_group;");

        uint32_t S = sb0 + buf * STG_B;
        #pragma unroll
        for (int sub = 0; sub < 2; sub++) {
            uint32_t aadr = S + (sub ? aoff1 : aoff0);
            uint32_t badr = S + 8192 + (sub ? boff1 : boff0);
            uint32_t ah[4][4];
            #pragma unroll
            for (int im = 0; im < 4; im++) ldsm4(ah[im], aadr + im * 1024);
            uint32_t b0[4], b1[4];
            ldsm4(b0, badr);
            ldsm4(b1, badr + 1024);
            #pragma unroll
            for (int im = 0; im < 4; im++) {
                hmma(acc[im][0], ah[im], b0);
                hmma(acc[im][1], ah[im], b0 + 2);
                hmma(acc[im][2], ah[im], b1);
                hmma(acc[im][3], ah[im], b1 + 2);
            }
        }
        if (++buf == NSTG) buf = 0;
    }

    // ---- epilogue ----
    #pragma unroll
    for (int im = 0; im < 4; im++) {
        #pragma unroll
        for (int half = 0; half < 2; half++) {
            int m = m0 + warp_m * 64 + im * 16 + lr + half * 8;
            if (m >= rows) continue;
            size_t crow = (size_t)(base + m) * (size_t)ldc;
            if (MODE == 0) crow = (size_t)m * ldc;
            #pragma unroll
            for (int in = 0; in < 4; in++) {
                int n = n0 + warp_n * 32 + in * 8 + lc * 2;
                float v0 = acc[im][in][half * 2];
                float v1 = acc[im][in][half * 2 + 1];
                if (EPI == 1) {
                    v0 = 0.5f * v0 * (1.0f + erff(v0 * 0.70710678118654752f));
                    v1 = 0.5f * v1 * (1.0f + erff(v1 * 0.70710678118654752f));
                    __half2 hv = __halves2half2(__float2half_rn(v0), __float2half_rn(v1));
                    *(__half2*)(Ch + crow + n) = hv;
                } else {
                    if (EPI == 2) {
                        v0 += addsrc[(size_t)m * ldadd + n];
                        v1 += addsrc[(size_t)m * ldadd + n + 1];
                    } else if (EPI == 3) {
                        float z0 = v0 + bias[n], z1 = v1 + bias[n + 1];
                        v0 = (z0 > 20.f) ? z0 : log1pf(__expf(z0));
                        v1 = (z1 > 20.f) ? z1 : log1pf(__expf(z1));
                    }
                    *(float2*)(C + crow + n) = make_float2(v0, v1);
                }
            }
        }
    }
}

// ---------------- rmsnorm (writes fp32 + fp16) ----------------
__global__ void rmsnorm_h(const float* __restrict__ x, float* __restrict__ o,
                          __half* __restrict__ oh)
{
    int row = blockIdx.x;
    const float4* xp = (const float4*)(x + (size_t)row * DMODEL);
    float4 v = xp[threadIdx.x];
    float s = v.x * v.x + v.y * v.y + v.z * v.z + v.w * v.w;
    __shared__ float ssum[8];
    #pragma unroll
    for (int off = 16; off; off >>= 1) s += __shfl_xor_sync(0xffffffffu, s, off);
    if ((threadIdx.x & 31) == 0) ssum[threadIdx.x >> 5] = s;
    __syncthreads();
    if (threadIdx.x < 8) {
        float t = ssum[threadIdx.x];
        #pragma unroll
        for (int off = 4; off; off >>= 1) t += __shfl_xor_sync(0xffu, t, off);
        if (threadIdx.x == 0) ssum[0] = t;
    }
    __syncthreads();
    float scale = 32.0f / fmaxf(sqrtf(ssum[0]), 1e-12f);
    float4 w = make_float4(v.x * scale, v.y * scale, v.z * scale, v.w * scale);
    ((float4*)(o + (size_t)row * DMODEL))[threadIdx.x] = w;
    ((uint2*)(oh + (size_t)row * DMODEL))[threadIdx.x] = cvt4(w);
}

// ---------------- split-K SIMT GEMM for skinny x_proj (exact fp32) ----------------
__global__ void __launch_bounds__(256) gemm_sk(
    const float* __restrict__ A, int lda,
    const float* __restrict__ W, int ldw,
    float* __restrict__ Cpart, int ldc,
    int M, int N, int kchunk)
{
    int koff = blockIdx.z * kchunk;
    float* C = Cpart + (size_t)blockIdx.z * M * ldc;
    __shared__ float As[16][68];
    __shared__ float Bs[16][68];
    int tid = threadIdx.x;
    int m0 = blockIdx.x * 64, n0 = blockIdx.y * 64;
    int tx = tid & 15, ty = tid >> 4;
    int lr = tid >> 2;
    int lk = (tid & 3) << 2;
    int am = m0 + lr;
    int wn = n0 + lr;
    bool a_ok = am < M;
    bool w_ok = wn < N;
    const float* Arow = A + (size_t)(a_ok ? am : 0) * lda + koff;
    const float* Wrow = W + (size_t)(w_ok ? wn : 0) * ldw + koff;
    float acc[4][4] = {};
    for (int k0 = 0; k0 < kchunk; k0 += 16) {
        float4 av = a_ok ? *(const float4*)(Arow + k0 + lk) : make_float4(0, 0, 0, 0);
        float4 wv = w_ok ? *(const float4*)(Wrow + k0 + lk) : make_float4(0, 0, 0, 0);
        __syncthreads();
        As[lk][lr] = av.x; As[lk + 1][lr] = av.y; As[lk + 2][lr] = av.z; As[lk + 3][lr] = av.w;
        Bs[lk][lr] = wv.x; Bs[lk + 1][lr] = wv.y; Bs[lk + 2][lr] = wv.z; Bs[lk + 3][lr] = wv.w;
        __syncthreads();
        #pragma unroll
        for (int k = 0; k < 16; k++) {
            float a[4], b[4];
            #pragma unroll
            for (int i = 0; i < 4; i++) a[i] = As[k][ty * 4 + i];
            #pragma unroll
            for (int j = 0; j < 4; j++) b[j] = Bs[k][tx * 4 + j];
            #pragma unroll
            for (int i = 0; i < 4; i++)
                #pragma unroll
                for (int j = 0; j < 4; j++)
                    acc[i][j] += a[i] * b[j];
        }
    }
    #pragma unroll
    for (int i = 0; i < 4; i++) {
        int m = m0 + ty * 4 + i;
        if (m >= M) continue;
        #pragma unroll
        for (int j = 0; j < 4; j++) {
            int n = n0 + tx * 4 + j;
            if (n >= N) continue;
            C[(size_t)m * ldc + n] = acc[i][j];
        }
    }
}

__global__ void reduce_sk(const float* __restrict__ p, float* __restrict__ o,
                          __half* __restrict__ oh, int n)
{
    int i = blockIdx.x * 256 + threadIdx.x;
    if (i >= n) return;
    float s = 0.f;
    #pragma unroll
    for (int j = 0; j < SPLITK; j++) s += p[i + (size_t)j * n];
    o[i] = s;
    oh[i] = __float2half_rn(s);
}

// ---------------- causal depthwise conv(4) + silu ----------------
__global__ void conv_silu(const float* __restrict__ xr, const float* __restrict__ cw,
                          const float* __restrict__ cb, float* __restrict__ u)
{
    int idx = blockIdx.x * 256 + threadIdx.x;
    int t = idx >> 11, d = idx & (DINNER - 1);
    float w0 = cw[d * 4], w1 = cw[d * 4 + 1], w2 = cw[d * 4 + 2], w3 = cw[d * 4 + 3];
    float s = cb[d];
    const float* col = xr + d;
    if (t >= 3) s += col[(size_t)(t - 3) * (2 * DINNER)] * w0;
    if (t >= 2) s += col[(size_t)(t - 2) * (2 * DINNER)] * w1;
    if (t >= 1) s += col[(size_t)(t - 1) * (2 * DINNER)] * w2;
    s += col[(size_t)t * (2 * DINNER)] * w3;
    u[idx] = s / (1.f + __expf(-s));
}

// ---------------- selective scan (fp16 y out) ----------------
__global__ void scan_kernel(const float* __restrict__ delta,
                            const float* __restrict__ u,
                            const float* __restrict__ xdbl,
                            const float* __restrict__ A_log,
                            const float* __restrict__ Dvec,
                            const float* __restrict__ xr,
                            __half* __restrict__ yh)
{
    int lane16 = threadIdx.x & 15;
    int ch = threadIdx.x >> 4;
    int d = blockIdx.x * 8 + ch;
    float A = -__expf(A_log[d * DSTATE + lane16]);
    float Dd = Dvec[d];
    float h = 0.f;
    __shared__ float sB[32][16], sC[32][16], sdl[32][8], su[32][8], sre[32][8];
    for (int t0 = 0; t0 < LSEQ; t0 += 32) {
        __syncthreads();
        for (int i = threadIdx.x; i < 512; i += 128) {
            int tt = i >> 4, n = i & 15;
            const float* xb = xdbl + (size_t)(t0 + tt) * XDBL;
            sB[tt][n] = xb[DTRANK + n];
            sC[tt][n] = xb[DTRANK + DSTATE + n];
        }
        for (int i = threadIdx.x; i < 256; i += 128) {
            int tt = i >> 3, c = i & 7;
            int dd = blockIdx.x * 8 + c;
            size_t off = (size_t)(t0 + tt) * DINNER + dd;
            sdl[tt][c] = delta[off];
            su[tt][c]  = u[off];
            sre[tt][c] = xr[(size_t)(t0 + tt) * (2 * DINNER) + DINNER + dd];
        }
        __syncthreads();
        for (int tt = 0; tt < 32; tt++) {
            float dl = sdl[tt][ch];
            float uu = su[tt][ch];
            float dA = __expf(dl * A);
            h = dA * h + dl * sB[tt][lane16] * uu;
            float p = h * sC[tt][lane16];
            #pragma unroll
            for (int o = 8; o; o >>= 1) p += __shfl_xor_sync(0xffffffffu, p, o, 16);
            if (lane16 == 0) {
                float yv = p + uu * Dd;
                float r = sre[tt][ch];
                yv *= r / (1.f + __expf(-r));
                yh[(size_t)(t0 + tt) * DINNER + d] = __float2half_rn(yv);
            }
        }
    }
}

// ---------------- gating: GEMV + softmax + top-2 ----------------
__global__ void gate_topk(const float* __restrict__ X, const float* __restrict__ gw,
                          int* __restrict__ te, float* __restrict__ tv)
{
    __shared__ float sg[NEXP * DMODEL];
    for (int i = threadIdx.x; i < NEXP * DMODEL; i += 128) sg[i] = gw[i];
    __syncthreads();
    int warp = threadIdx.x >> 5, lane = threadIdx.x & 31;
    int t = blockIdx.x * 4 + warp;
    const float* xp = X + (size_t)t * DMODEL;
    float acc[NEXP] = {};
    for (int k = lane; k < DMODEL; k += 32) {
        float xv = xp[k];
        #pragma unroll
        for (int e = 0; e < NEXP; e++) acc[e] += xv * sg[e * DMODEL + k];
    }
    #pragma unroll
    for (int e = 0; e < NEXP; e++)
        #pragma unroll
        for (int o = 16; o; o >>= 1) acc[e] += __shfl_xor_sync(0xffffffffu, acc[e], o);
    if (lane == 0) {
        float m = acc[0];
        #pragma unroll
        for (int e = 1; e < NEXP; e++) m = fmaxf(m, acc[e]);
        float g[NEXP];
        #pragma unroll
        for (int e = 0; e < NEXP; e++) g[e] = __expf(acc[e] - m);
        int i0 = 0;
        #pragma unroll
        for (int e = 1; e < NEXP; e++) if (g[e] > g[i0]) i0 = e;
        int i1 = (i0 == 0) ? 1 : 0;
        #pragma unroll
        for (int e = 0; e < NEXP; e++) if (e != i0 && g[e] > g[i1]) i1 = e;
        float inv = 1.f / (g[i0] + g[i1]);
        te[t * 2] = i0; te[t * 2 + 1] = i1;
        tv[t * 2] = g[i0] * inv; tv[t * 2 + 1] = g[i1] * inv;
    }
}

// ---------------- fused routing: count + offsets + scatter (1 CTA) ----------------
__global__ void __launch_bounds__(256) route_all(
    const int* __restrict__ te, const float* __restrict__ tv,
    int* __restrict__ off, int* __restrict__ ptok, float* __restrict__ pw,
    int* __restrict__ tok_pair)
{
    __shared__ int scnt[NEXP], soff[NEXP + 1], scur[NEXP];
    int tid = threadIdx.x;
    if (tid < NEXP) scnt[tid] = 0;
    __syncthreads();
    for (int t = tid; t < LSEQ; t += 256) {
        atomicAdd(&scnt[te[t * 2]], 1);
        atomicAdd(&scnt[te[t * 2 + 1]], 1);
    }
    __syncthreads();
    if (tid == 0) {
        int s = 0;
        #pragma unroll
        for (int e = 0; e < NEXP; e++) { soff[e] = s; scur[e] = 0; s += scnt[e]; }
        soff[NEXP] = s;
    }
    __syncthreads();
    if (tid < NEXP + 1) off[tid] = soff[tid];
    for (int t = tid; t < LSEQ; t += 256) {
        #pragma unroll
        for (int k = 0; k < 2; k++) {
            int e = te[t * 2 + k];
            int pos = atomicAdd(&scur[e], 1);
            int p = soff[e] + pos;
            ptok[p] = t;
            pw[p] = tv[t * 2 + k];
            tok_pair[t * 2 + k] = p;
        }
    }
}

// ---------------- final combine ----------------
__global__ void moe_combine(const float* __restrict__ x, const float* __restrict__ y2,
                            const int* __restrict__ tok_pair, const float* __restrict__ pw,
                            float* __restrict__ out)
{
    int i = blockIdx.x * 256 + threadIdx.x;
    int t = i >> 10, n = i & (DMODEL - 1);
    int p0 = tok_pair[t * 2], p1 = tok_pair[t * 2 + 1];
    out[i] = x[i] + pw[p0] * y2[(size_t)p0 * DMODEL + n]
                  + pw[p1] * y2[(size_t)p1 * DMODEL + n];
}

// ---------------- launch ----------------
extern "C" void kernel_launch(void* const* d_in, const int* in_sizes, int n_in,
                              void* d_out, int out_size)
{
    (void)in_sizes; (void)n_in; (void)out_size;
    const float* x          = (const float*)d_in[0];
    const float* in_proj_w  = (const float*)d_in[1];
    const float* conv_w     = (const float*)d_in[2];
    const float* conv_b     = (const float*)d_in[3];
    const float* x_proj_w   = (const float*)d_in[4];
    const float* dt_proj_w  = (const float*)d_in[5];
    const float* dt_proj_b  = (const float*)d_in[6];
    const float* A_log      = (const float*)d_in[7];
    const float* Dvec       = (const float*)d_in[8];
    const float* out_proj_w = (const float*)d_in[9];
    const float* gate_w     = (const float*)d_in[10];
    const float* w1         = (const float*)d_in[11];
    const float* w2         = (const float*)d_in[12];
    float* out = (float*)d_out;

    float *p_xn, *p_xr, *p_u, *p_xdbl, *p_xp, *p_delta, *p_xm2, *p_xm2n, *p_y2, *p_tv, *p_pw;
    int *p_te, *p_off, *p_ptok, *p_tp;
    cudaGetSymbolAddress((void**)&p_xn, g_xn);
    cudaGetSymbolAddress((void**)&p_xr, g_xr);
    cudaGetSymbolAddress((void**)&p_u, g_u);
    cudaGetSymbolAddress((void**)&p_xdbl, g_xdbl);
    cudaGetSymbolAddress((void**)&p_xp, g_xp);
    cudaGetSymbolAddress((void**)&p_delta, g_delta);
    cudaGetSymbolAddress((void**)&p_xm2, g_xm2);
    cudaGetSymbolAddress((void**)&p_xm2n, g_xm2n);
    cudaGetSymbolAddress((void**)&p_y2, g_y2);
    cudaGetSymbolAddress((void**)&p_te, g_top_e);
    cudaGetSymbolAddress((void**)&p_tv, g_top_v);
    cudaGetSymbolAddress((void**)&p_off, g_off);
    cudaGetSymbolAddress((void**)&p_ptok, g_ptok);
    cudaGetSymbolAddress((void**)&p_pw, g_pw);
    cudaGetSymbolAddress((void**)&p_tp, g_tok_pair);

    __half *xnh, *xdh, *yh, *x2h, *hh;
    cudaGetSymbolAddress((void**)&xnh, h_xn);
    cudaGetSymbolAddress((void**)&xdh, h_xd);
    cudaGetSymbolAddress((void**)&yh,  h_y);
    cudaGetSymbolAddress((void**)&x2h, h_x2);
    cudaGetSymbolAddress((void**)&hh,  h_h);

    const int SMEM = NSTG * STG_B;   // 48 KB
    cudaFuncSetAttribute((const void*)hgemm<0, 0>, cudaFuncAttributeMaxDynamicSharedMemorySize, SMEM);
    cudaFuncSetAttribute((const void*)hgemm<3, 0>, cudaFuncAttributeMaxDynamicSharedMemorySize, SMEM);
    cudaFuncSetAttribute((const void*)hgemm<2, 0>, cudaFuncAttributeMaxDynamicSharedMemorySize, SMEM);
    cudaFuncSetAttribute((const void*)hgemm<1, 1>, cudaFuncAttributeMaxDynamicSharedMemorySize, SMEM);
    cudaFuncSetAttribute((const void*)hgemm<0, 2>, cudaFuncAttributeMaxDynamicSharedMemorySize, SMEM);

    // 1. xn = rmsnorm(x)
    rmsnorm_h<<<LSEQ, 256>>>(x, p_xn, xnh);
    // 2. xr = xn @ in_proj^T (2048x4096, K=1024)  [fp32 W converted in-kernel]
    hgemm<0, 0><<<dim3(16, 32), 256, SMEM>>>(xnh, DMODEL, in_proj_w, DMODEL,
                                             p_xr, 2 * DINNER, LSEQ, 2 * DINNER,
                                             nullptr, nullptr, 0, nullptr, nullptr, nullptr);
    // 3. conv + silu
    conv_silu<<<(LSEQ * DINNER) / 256, 256>>>(p_xr, conv_w, conv_b, p_u);
    // 4. x_dbl = u @ x_proj^T (2048x96, K=2048) split-K exact fp32
    gemm_sk<<<dim3(32, 2, SPLITK), 256>>>(p_u, DINNER, x_proj_w, DINNER,
                                          p_xp, XDBL, LSEQ, XDBL, DINNER / SPLITK);
    reduce_sk<<<(LSEQ * XDBL + 255) / 256, 256>>>(p_xp, p_xdbl, xdh, LSEQ * XDBL);
    // 5. delta = softplus(dt @ dt_proj^T + b) (2048x2048, K=64)
    hgemm<3, 0><<<dim3(16, 16), 256, SMEM>>>(xdh, XDBL, dt_proj_w, DTRANK,
                                             p_delta, DINNER, LSEQ, DINNER,
                                             dt_proj_b, nullptr, 0, nullptr, nullptr, nullptr);
    // 6. selective scan -> y fp16
    scan_kernel<<<DINNER / 8, 128>>>(p_delta, p_u, p_xdbl, A_log, Dvec, p_xr, yh);
    // 7. xm2 = y @ out_proj^T + xn (2048x1024, K=2048)
    hgemm<2, 0><<<dim3(16, 8), 256, SMEM>>>(yh, DINNER, out_proj_w, DINNER,
                                            p_xm2, DMODEL, LSEQ, DMODEL,
                                            nullptr, p_xn, DMODEL, nullptr, nullptr, nullptr);
    // 8. xm2n = rmsnorm(xm2)
    rmsnorm_h<<<LSEQ, 256>>>(p_xm2, p_xm2n, x2h);
    // 9. gating + routing (fused)
    gate_topk<<<LSEQ / 4, 128>>>(p_xm2n, gate_w, p_te, p_tv);
    route_all<<<1, 256>>>(p_te, p_tv, p_off, p_ptok, p_pw, p_tp);
    // 10. expert GEMMs (fp32 weights, converted in-kernel)
    hgemm<1, 1><<<dim3(32, 32, NEXP), 256, SMEM>>>(x2h, DMODEL, w1, DMODEL,
                                                   nullptr, HIDDEN, 0, HIDDEN,
                                                   nullptr, nullptr, 0, p_off, p_ptok, hh);
    hgemm<0, 2><<<dim3(32, 8, NEXP), 256, SMEM>>>(hh, HIDDEN, w2, HIDDEN,
                                                  p_y2, DMODEL, 0, DMODEL,
                                                  nullptr, nullptr, 0, p_off, nullptr, nullptr);
    moe_combine<<<(LSEQ * DMODEL) / 256, 256>>>(x, p_y2, p_tp, p_pw, out);
}

// round 14
// speedup vs baseline: 1.0231x; 1.0231x over previous
#include <cuda_runtime.h>
#include <cuda_fp16.h>
#include <math.h>
#include <stdint.h>

// ---------------- problem constants ----------------
#define LSEQ   2048
#define DMODEL 1024
#define DINNER 2048
#define DSTATE 16
#define DTRANK 64
#define XDBL   96
#define NEXP   8
#define HIDDEN 4096
#define NPAIR  4096
#define SPLITK 16

// ---------------- fp32 scratch ----------------
__device__ float g_xn   [LSEQ * DMODEL];
__device__ float g_xr   [LSEQ * 2 * DINNER];
__device__ float g_u    [LSEQ * DINNER];
__device__ float g_xdbl [LSEQ * XDBL];
__device__ float g_xp   [SPLITK * LSEQ * XDBL];
__device__ float g_delta[LSEQ * DINNER];
__device__ float g_xm2  [LSEQ * DMODEL];
__device__ float g_xm2n [LSEQ * DMODEL];
__device__ float g_y2   [(size_t)NPAIR * DMODEL];
__device__ int   g_top_e[LSEQ * 2];
__device__ float g_top_v[LSEQ * 2];
__device__ int   g_off[NEXP + 1];
__device__ int   g_ptok[NPAIR];
__device__ float g_pw  [NPAIR];
__device__ int   g_tok_pair[LSEQ * 2];

// ---------------- fp16 scratch ----------------
__device__ __align__(16) __half h_xn [LSEQ * DMODEL];
__device__ __align__(16) __half h_xd [LSEQ * XDBL];
__device__ __align__(16) __half h_y  [LSEQ * DINNER];
__device__ __align__(16) __half h_x2 [LSEQ * DMODEL];
__device__ __align__(16) __half h_h  [(size_t)NPAIR * HIDDEN];
__device__ __align__(16) __half h_wi [2 * DINNER * DMODEL];
__device__ __align__(16) __half h_wd [DINNER * DTRANK];
__device__ __align__(16) __half h_wo [DMODEL * DINNER];

// ---------------- helpers ----------------
__device__ __forceinline__ void cpa16(uint32_t dst, const void* src)
{
    asm volatile("cp.async.cg.shared.global [%0], [%1], 16;" :: "r"(dst), "l"(src));
}

__device__ __forceinline__ void ldsm4(uint32_t* r, uint32_t a)
{
    asm volatile("ldmatrix.sync.aligned.m8n8.x4.shared.b16 {%0,%1,%2,%3}, [%4];"
                 : "=r"(r[0]), "=r"(r[1]), "=r"(r[2]), "=r"(r[3]) : "r"(a));
}

__device__ __forceinline__ void hmma(float* d, const uint32_t* a, const uint32_t* b)
{
    asm volatile(
        "mma.sync.aligned.m16n8k16.row.col.f32.f16.f16.f32 "
        "{%0,%1,%2,%3},{%4,%5,%6,%7},{%8,%9},{%0,%1,%2,%3};\n"
        : "+f"(d[0]), "+f"(d[1]), "+f"(d[2]), "+f"(d[3])
        : "r"(a[0]), "r"(a[1]), "r"(a[2]), "r"(a[3]), "r"(b[0]), "r"(b[1]));
}

__device__ __forceinline__ uint2 cvt4(float4 v)
{
    __half2 h01 = __halves2half2(__float2half_rn(v.x), __float2half_rn(v.y));
    __half2 h23 = __halves2half2(__float2half_rn(v.z), __float2half_rn(v.w));
    return make_uint2(*(uint32_t*)&h01, *(uint32_t*)&h23);
}

__device__ __forceinline__ uint4 cvt8(float4 a, float4 b)
{
    uint2 lo = cvt4(a), hi = cvt4(b);
    return make_uint4(lo.x, lo.y, hi.x, hi.y);
}

// ---------------- weight convert: fp32 -> fp16 ----------------
__global__ void conv_h(const float4* __restrict__ src, uint2* __restrict__ dst, int n4)
{
    int i = blockIdx.x * 256 + threadIdx.x;
    if (i >= n4) return;
    dst[i] = cvt4(src[i]);
}

// ---------------- fp16 tensor GEMM: C = epi(A @ W^T) ----------------
// A: (M,K) fp16 row-major stride lda. W: fp16 (BCVT=0) or fp32 (BCVT=1), (N,K) stride K.
// CTA tile 128x128, k-stage 32, 3-stage cp.async pipeline (1 sync/iter).
// BCVT=1: B loaded fp32 via LDG, converted to fp16 in-register, STS'd one stage ahead.
// EPI: 0 store fp32, 1 gelu->fp16, 2 +addsrc fp32, 3 softplus(+bias) fp32
// MODE: 0 plain, 1 gather A rows via ptok + per-expert W, 2 contiguous expert rows
#define NSTG 3
#define STG_B 16384
template<int EPI, int MODE, int BCVT>
__global__ void __launch_bounds__(256, 2) hgemm(
    const __half* __restrict__ Aq, int lda,
    const __half* __restrict__ Wq, const float* __restrict__ Wf, int K,
    float* __restrict__ C, int ldc, int M, int N,
    const float* __restrict__ bias, const float* __restrict__ addsrc, int ldadd,
    const int* __restrict__ off, const int* __restrict__ ptok,
    __half* __restrict__ Ch)
{
    extern __shared__ __align__(16) uint8_t smem[];
    int base = 0, rows = M;
    const __half* W = Wq;
    const float* WF = Wf;
    if (MODE != 0) {
        int e = blockIdx.z;
        base = off[e];
        rows = off[e + 1] - base;
        if (BCVT) WF += (size_t)e * (size_t)N * K;
        else      W  += (size_t)e * (size_t)N * K;
    }
    int m0 = blockIdx.x * 128;
    if (m0 >= rows) return;
    int n0 = blockIdx.y * 128;

    int tid = threadIdx.x;
    int wid = tid >> 5, lane = tid & 31;
    int lr = lane >> 2, lc = lane & 3;
    int warp_m = wid >> 2, warp_n = wid & 3;

    // ---- global load mapping ----
    int qg = tid & 3;
    int ar = tid >> 2;                 // 0..63
    int rA0 = m0 + ar, rA1 = rA0 + 64;
    int c0 = rA0 < rows ? rA0 : rows - 1;
    int c1 = rA1 < rows ? rA1 : rows - 1;
    int gA0, gA1;
    if (MODE == 1)      { gA0 = ptok[base + c0]; gA1 = ptok[base + c1]; }
    else if (MODE == 2) { gA0 = base + c0;       gA1 = base + c1; }
    else                { gA0 = c0;              gA1 = c1; }

    const __half* pA0 = Aq + (size_t)gA0 * lda + qg * 8;
    const __half* pA1 = Aq + (size_t)gA1 * lda + qg * 8;
    const __half* pB0h = BCVT ? nullptr : (W + (size_t)(n0 + ar) * K + qg * 8);
    const __half* pB1h = BCVT ? nullptr : (W + (size_t)(n0 + ar + 64) * K + qg * 8);
    const float*  pB0f = BCVT ? (WF + (size_t)(n0 + ar) * K + qg * 8) : nullptr;
    const float*  pB1f = BCVT ? (WF + (size_t)(n0 + ar + 64) * K + qg * 8) : nullptr;

    uint32_t sb0 = (uint32_t)__cvta_generic_to_shared(smem);
    int dst0 = ar * 64 + ((qg ^ ((ar >> 1) & 3)) << 4);
    int dst1 = dst0 + 4096;

    // ---- per-lane ldmatrix addresses ----
    int rA = warp_m * 64 + (lane & 15);
    int swzA = (rA >> 1) & 3;
    int aoff0 = rA * 64 + ((((lane >> 4)) ^ swzA) << 4);
    int aoff1 = rA * 64 + (((2 + (lane >> 4)) ^ swzA) << 4);
    int rB = warp_n * 32 + (lane & 7) + ((lane >> 4) << 3);
    int swzB = (rB >> 1) & 3;
    int boff0 = rB * 64 + ((((lane >> 3) & 1) ^ swzB) << 4);
    int boff1 = rB * 64 + (((2 + ((lane >> 3) & 1)) ^ swzB) << 4);

    float acc[4][4][4];
    #pragma unroll
    for (int i = 0; i < 4; i++)
        #pragma unroll
        for (int j = 0; j < 4; j++)
            #pragma unroll
            for (int r = 0; r < 4; r++) acc[i][j][r] = 0.f;

    int nt = K >> 5;
    float4 br[4];   // staged fp32 B (BCVT only)
    // prologue: stages 0 and 1
    if (BCVT) {
        br[0] = __ldg((const float4*)pB0f);
        br[1] = __ldg((const float4*)(pB0f + 4));
        br[2] = __ldg((const float4*)pB1f);
        br[3] = __ldg((const float4*)(pB1f + 4));
        *(uint4*)(smem + 8192 + dst0) = cvt8(br[0], br[1]);
        *(uint4*)(smem + 8192 + dst1) = cvt8(br[2], br[3]);
        cpa16(sb0 + dst0, pA0);
        cpa16(sb0 + dst1, pA1);
        asm volatile("cp.async.commit_group;");
        if (nt > 1) {
            br[0] = __ldg((const float4*)(pB0f + 32));
            br[1] = __ldg((const float4*)(pB0f + 36));
            br[2] = __ldg((const float4*)(pB1f + 32));
            br[3] = __ldg((const float4*)(pB1f + 36));
            uint32_t s = sb0 + STG_B;
            cpa16(s + dst0, pA0 + 32);
            cpa16(s + dst1, pA1 + 32);
        }
        asm volatile("cp.async.commit_group;");
    } else {
        cpa16(sb0 + 0    + dst0, pA0);
        cpa16(sb0 + 0    + dst1, pA1);
        cpa16(sb0 + 8192 + dst0, pB0h);
        cpa16(sb0 + 8192 + dst1, pB1h);
        asm volatile("cp.async.commit_group;");
        if (nt > 1) {
            uint32_t s = sb0 + STG_B;
            cpa16(s + 0    + dst0, pA0 + 32);
            cpa16(s + 0    + dst1, pA1 + 32);
            cpa16(s + 8192 + dst0, pB0h + 32);
            cpa16(s + 8192 + dst1, pB1h + 32);
        }
        asm volatile("cp.async.commit_group;");
    }
    int buf = 0;
    for (int t = 0; t < nt; t++) {
        asm volatile("cp.async.wait_group 1;");
        __syncthreads();
        if (BCVT) {
            if (t + 1 < nt) {
                int nb1 = buf + 1; if (nb1 >= NSTG) nb1 -= NSTG;
                *(uint4*)(smem + nb1 * STG_B + 8192 + dst0) = cvt8(br[0], br[1]);
                *(uint4*)(smem + nb1 * STG_B + 8192 + dst1) = cvt8(br[2], br[3]);
            }
            if (t + 2 < nt) {
                int kc = (t + 2) << 5;
                br[0] = __ldg((const float4*)(pB0f + kc));
                br[1] = __ldg((const float4*)(pB0f + kc + 4));
                br[2] = __ldg((const float4*)(pB1f + kc));
                br[3] = __ldg((const float4*)(pB1f + kc + 4));
                int nb = buf + 2; if (nb >= NSTG) nb -= NSTG;
                uint32_t s = sb0 + nb * STG_B;
                cpa16(s + dst0, pA0 + kc);
                cpa16(s + dst1, pA1 + kc);
            }
        } else if (t + 2 < nt) {
            int kc = (t + 2) << 5;
            int nb = buf + 2; if (nb >= NSTG) nb -= NSTG;
            uint32_t s = sb0 + nb * STG_B;
            cpa16(s + 0    + dst0, pA0 + kc);
            cpa16(s + 0    + dst1, pA1 + kc);
            cpa16(s + 8192 + dst0, pB0h + kc);
            cpa16(s + 8192 + dst1, pB1h + kc);
        }
        asm volatile("cp.async.commit_group;");

        uint32_t S = sb0 + buf * STG_B;
        #pragma unroll
        for (int sub = 0; sub < 2; sub++) {
            uint32_t aadr = S + (sub ? aoff1 : aoff0);
            uint32_t badr = S + 8192 + (sub ? boff1 : boff0);
            uint32_t ah[4][4];
            #pragma unroll
            for (int im = 0; im < 4; im++) ldsm4(ah[im], aadr + im * 1024);
            uint32_t b0[4], b1[4];
            ldsm4(b0, badr);
            ldsm4(b1, badr + 1024);
            #pragma unroll
            for (int im = 0; im < 4; im++) {
                hmma(acc[im][0], ah[im], b0);
                hmma(acc[im][1], ah[im], b0 + 2);
                hmma(acc[im][2], ah[im], b1);
                hmma(acc[im][3], ah[im], b1 + 2);
            }
        }
        if (++buf == NSTG) buf = 0;
    }

    // ---- epilogue ----
    #pragma unroll
    for (int im = 0; im < 4; im++) {
        #pragma unroll
        for (int half = 0; half < 2; half++) {
            int m = m0 + warp_m * 64 + im * 16 + lr + half * 8;
            if (m >= rows) continue;
            size_t crow = (size_t)(base + m) * (size_t)ldc;
            if (MODE == 0) crow = (size_t)m * ldc;
            #pragma unroll
            for (int in = 0; in < 4; in++) {
                int n = n0 + warp_n * 32 + in * 8 + lc * 2;
                float v0 = acc[im][in][half * 2];
                float v1 = acc[im][in][half * 2 + 1];
                if (EPI == 1) {
                    v0 = 0.5f * v0 * (1.0f + erff(v0 * 0.70710678118654752f));
                    v1 = 0.5f * v1 * (1.0f + erff(v1 * 0.70710678118654752f));
                    __half2 hv = __halves2half2(__float2half_rn(v0), __float2half_rn(v1));
                    *(__half2*)(Ch + crow + n) = hv;
                } else {
                    if (EPI == 2) {
                        v0 += addsrc[(size_t)m * ldadd + n];
                        v1 += addsrc[(size_t)m * ldadd + n + 1];
                    } else if (EPI == 3) {
                        float z0 = v0 + bias[n], z1 = v1 + bias[n + 1];
                        v0 = (z0 > 20.f) ? z0 : log1pf(__expf(z0));
                        v1 = (z1 > 20.f) ? z1 : log1pf(__expf(z1));
                    }
                    *(float2*)(C + crow + n) = make_float2(v0, v1);
                }
            }
        }
    }
}

// ---------------- rmsnorm (writes fp32 + fp16) ----------------
__global__ void rmsnorm_h(const float* __restrict__ x, float* __restrict__ o,
                          __half* __restrict__ oh)
{
    int row = blockIdx.x;
    const float4* xp = (const float4*)(x + (size_t)row * DMODEL);
    float4 v = xp[threadIdx.x];
    float s = v.x * v.x + v.y * v.y + v.z * v.z + v.w * v.w;
    __shared__ float ssum[8];
    #pragma unroll
    for (int off = 16; off; off >>= 1) s += __shfl_xor_sync(0xffffffffu, s, off);
    if ((threadIdx.x & 31) == 0) ssum[threadIdx.x >> 5] = s;
    __syncthreads();
    if (threadIdx.x < 8) {
        float t = ssum[threadIdx.x];
        #pragma unroll
        for (int off = 4; off; off >>= 1) t += __shfl_xor_sync(0xffu, t, off);
        if (threadIdx.x == 0) ssum[0] = t;
    }
    __syncthreads();
    float scale = 32.0f / fmaxf(sqrtf(ssum[0]), 1e-12f);
    float4 w = make_float4(v.x * scale, v.y * scale, v.z * scale, v.w * scale);
    ((float4*)(o + (size_t)row * DMODEL))[threadIdx.x] = w;
    ((uint2*)(oh + (size_t)row * DMODEL))[threadIdx.x] = cvt4(w);
}

// ---------------- split-K SIMT GEMM for skinny x_proj (exact fp32) ----------------
__global__ void __launch_bounds__(256) gemm_sk(
    const float* __restrict__ A, int lda,
    const float* __restrict__ W, int ldw,
    float* __restrict__ Cpart, int ldc,
    int M, int N, int kchunk)
{
    int koff = blockIdx.z * kchunk;
    float* C = Cpart + (size_t)blockIdx.z * M * ldc;
    __shared__ float As[16][68];
    __shared__ float Bs[16][68];
    int tid = threadIdx.x;
    int m0 = blockIdx.x * 64, n0 = blockIdx.y * 64;
    int tx = tid & 15, ty = tid >> 4;
    int lr = tid >> 2;
    int lk = (tid & 3) << 2;
    int am = m0 + lr;
    int wn = n0 + lr;
    bool a_ok = am < M;
    bool w_ok = wn < N;
    const float* Arow = A + (size_t)(a_ok ? am : 0) * lda + koff;
    const float* Wrow = W + (size_t)(w_ok ? wn : 0) * ldw + koff;
    float acc[4][4] = {};
    for (int k0 = 0; k0 < kchunk; k0 += 16) {
        float4 av = a_ok ? *(const float4*)(Arow + k0 + lk) : make_float4(0, 0, 0, 0);
        float4 wv = w_ok ? *(const float4*)(Wrow + k0 + lk) : make_float4(0, 0, 0, 0);
        __syncthreads();
        As[lk][lr] = av.x; As[lk + 1][lr] = av.y; As[lk + 2][lr] = av.z; As[lk + 3][lr] = av.w;
        Bs[lk][lr] = wv.x; Bs[lk + 1][lr] = wv.y; Bs[lk + 2][lr] = wv.z; Bs[lk + 3][lr] = wv.w;
        __syncthreads();
        #pragma unroll
        for (int k = 0; k < 16; k++) {
            float a[4], b[4];
            #pragma unroll
            for (int i = 0; i < 4; i++) a[i] = As[k][ty * 4 + i];
            #pragma unroll
            for (int j = 0; j < 4; j++) b[j] = Bs[k][tx * 4 + j];
            #pragma unroll
            for (int i = 0; i < 4; i++)
                #pragma unroll
                for (int j = 0; j < 4; j++)
                    acc[i][j] += a[i] * b[j];
        }
    }
    #pragma unroll
    for (int i = 0; i < 4; i++) {
        int m = m0 + ty * 4 + i;
        if (m >= M) continue;
        #pragma unroll
        for (int j = 0; j < 4; j++) {
            int n = n0 + tx * 4 + j;
            if (n >= N) continue;
            C[(size_t)m * ldc + n] = acc[i][j];
        }
    }
}

__global__ void reduce_sk(const float* __restrict__ p, float* __restrict__ o,
                          __half* __restrict__ oh, int n)
{
    int i = blockIdx.x * 256 + threadIdx.x;
    if (i >= n) return;
    float s = 0.f;
    #pragma unroll
    for (int j = 0; j < SPLITK; j++) s += p[i + (size_t)j * n];
    o[i] = s;
    oh[i] = __float2half_rn(s);
}

// ---------------- causal depthwise conv(4) + silu ----------------
__global__ void conv_silu(const float* __restrict__ xr, const float* __restrict__ cw,
                          const float* __restrict__ cb, float* __restrict__ u)
{
    int idx = blockIdx.x * 256 + threadIdx.x;
    int t = idx >> 11, d = idx & (DINNER - 1);
    float w0 = cw[d * 4], w1 = cw[d * 4 + 1], w2 = cw[d * 4 + 2], w3 = cw[d * 4 + 3];
    float s = cb[d];
    const float* col = xr + d;
    if (t >= 3) s += col[(size_t)(t - 3) * (2 * DINNER)] * w0;
    if (t >= 2) s += col[(size_t)(t - 2) * (2 * DINNER)] * w1;
    if (t >= 1) s += col[(size_t)(t - 1) * (2 * DINNER)] * w2;
    s += col[(size_t)t * (2 * DINNER)] * w3;
    u[idx] = s / (1.f + __expf(-s));
}

// ---------------- selective scan (fp16 y out) ----------------
__global__ void scan_kernel(const float* __restrict__ delta,
                            const float* __restrict__ u,
                            const float* __restrict__ xdbl,
                            const float* __restrict__ A_log,
                            const float* __restrict__ Dvec,
                            const float* __restrict__ xr,
                            __half* __restrict__ yh)
{
    int lane16 = threadIdx.x & 15;
    int ch = threadIdx.x >> 4;
    int d = blockIdx.x * 8 + ch;
    float A = -__expf(A_log[d * DSTATE + lane16]);
    float Dd = Dvec[d];
    float h = 0.f;
    __shared__ float sB[32][16], sC[32][16], sdl[32][8], su[32][8], sre[32][8];
    for (int t0 = 0; t0 < LSEQ; t0 += 32) {
        __syncthreads();
        for (int i = threadIdx.x; i < 512; i += 128) {
            int tt = i >> 4, n = i & 15;
            const float* xb = xdbl + (size_t)(t0 + tt) * XDBL;
            sB[tt][n] = xb[DTRANK + n];
            sC[tt][n] = xb[DTRANK + DSTATE + n];
        }
        for (int i = threadIdx.x; i < 256; i += 128) {
            int tt = i >> 3, c = i & 7;
            int dd = blockIdx.x * 8 + c;
            size_t off = (size_t)(t0 + tt) * DINNER + dd;
            sdl[tt][c] = delta[off];
            su[tt][c]  = u[off];
            sre[tt][c] = xr[(size_t)(t0 + tt) * (2 * DINNER) + DINNER + dd];
        }
        __syncthreads();
        for (int tt = 0; tt < 32; tt++) {
            float dl = sdl[tt][ch];
            float uu = su[tt][ch];
            float dA = __expf(dl * A);
            h = dA * h + dl * sB[tt][lane16] * uu;
            float p = h * sC[tt][lane16];
            #pragma unroll
            for (int o = 8; o; o >>= 1) p += __shfl_xor_sync(0xffffffffu, p, o, 16);
            if (lane16 == 0) {
                float yv = p + uu * Dd;
                float r = sre[tt][ch];
                yv *= r / (1.f + __expf(-r));
                yh[(size_t)(t0 + tt) * DINNER + d] = __float2half_rn(yv);
            }
        }
    }
}

// ---------------- gating: GEMV + softmax + top-2 ----------------
__global__ void gate_topk(const float* __restrict__ X, const float* __restrict__ gw,
                          int* __restrict__ te, float* __restrict__ tv)
{
    __shared__ float sg[NEXP * DMODEL];
    for (int i = threadIdx.x; i < NEXP * DMODEL; i += 128) sg[i] = gw[i];
    __syncthreads();
    int warp = threadIdx.x >> 5, lane = threadIdx.x & 31;
    int t = blockIdx.x * 4 + warp;
    const float* xp = X + (size_t)t * DMODEL;
    float acc[NEXP] = {};
    for (int k = lane; k < DMODEL; k += 32) {
        float xv = xp[k];
        #pragma unroll
        for (int e = 0; e < NEXP; e++) acc[e] += xv * sg[e * DMODEL + k];
    }
    #pragma unroll
    for (int e = 0; e < NEXP; e++)
        #pragma unroll
        for (int o = 16; o; o >>= 1) acc[e] += __shfl_xor_sync(0xffffffffu, acc[e], o);
    if (lane == 0) {
        float m = acc[0];
        #pragma unroll
        for (int e = 1; e < NEXP; e++) m = fmaxf(m, acc[e]);
        float g[NEXP];
        #pragma unroll
        for (int e = 0; e < NEXP; e++) g[e] = __expf(acc[e] - m);
        int i0 = 0;
        #pragma unroll
        for (int e = 1; e < NEXP; e++) if (g[e] > g[i0]) i0 = e;
        int i1 = (i0 == 0) ? 1 : 0;
        #pragma unroll
        for (int e = 0; e < NEXP; e++) if (e != i0 && g[e] > g[i1]) i1 = e;
        float inv = 1.f / (g[i0] + g[i1]);
        te[t * 2] = i0; te[t * 2 + 1] = i1;
        tv[t * 2] = g[i0] * inv; tv[t * 2 + 1] = g[i1] * inv;
    }
}

// ---------------- fused routing: count + offsets + scatter (1 CTA) ----------------
__global__ void __launch_bounds__(256) route_all(
    const int* __restrict__ te, const float* __restrict__ tv,
    int* __restrict__ off, int* __restrict__ ptok, float* __restrict__ pw,
    int* __restrict__ tok_pair)
{
    __shared__ int scnt[NEXP], soff[NEXP + 1], scur[NEXP];
    int tid = threadIdx.x;
    if (tid < NEXP) scnt[tid] = 0;
    __syncthreads();
    for (int t = tid; t < LSEQ; t += 256) {
        atomicAdd(&scnt[te[t * 2]], 1);
        atomicAdd(&scnt[te[t * 2 + 1]], 1);
    }
    __syncthreads();
    if (tid == 0) {
        int s = 0;
        #pragma unroll
        for (int e = 0; e < NEXP; e++) { soff[e] = s; scur[e] = 0; s += scnt[e]; }
        soff[NEXP] = s;
    }
    __syncthreads();
    if (tid < NEXP + 1) off[tid] = soff[tid];
    for (int t = tid; t < LSEQ; t += 256) {
        #pragma unroll
        for (int k = 0; k < 2; k++) {
            int e = te[t * 2 + k];
            int pos = atomicAdd(&scur[e], 1);
            int p = soff[e] + pos;
            ptok[p] = t;
            pw[p] = tv[t * 2 + k];
            tok_pair[t * 2 + k] = p;
        }
    }
}

// ---------------- final combine ----------------
__global__ void moe_combine(const float* __restrict__ x, const float* __restrict__ y2,
                            const int* __restrict__ tok_pair, const float* __restrict__ pw,
                            float* __restrict__ out)
{
    int i = blockIdx.x * 256 + threadIdx.x;
    int t = i >> 10, n = i & (DMODEL - 1);
    int p0 = tok_pair[t * 2], p1 = tok_pair[t * 2 + 1];
    out[i] = x[i] + pw[p0] * y2[(size_t)p0 * DMODEL + n]
                  + pw[p1] * y2[(size_t)p1 * DMODEL + n];
}

// ---------------- launch ----------------
extern "C" void kernel_launch(void* const* d_in, const int* in_sizes, int n_in,
                              void* d_out, int out_size)
{
    (void)in_sizes; (void)n_in; (void)out_size;
    const float* x          = (const float*)d_in[0];
    const float* in_proj_w  = (const float*)d_in[1];
    const float* conv_w     = (const float*)d_in[2];
    const float* conv_b     = (const float*)d_in[3];
    const float* x_proj_w   = (const float*)d_in[4];
    const float* dt_proj_w  = (const float*)d_in[5];
    const float* dt_proj_b  = (const float*)d_in[6];
    const float* A_log      = (const float*)d_in[7];
    const float* Dvec       = (const float*)d_in[8];
    const float* out_proj_w = (const float*)d_in[9];
    const float* gate_w     = (const float*)d_in[10];
    const float* w1         = (const float*)d_in[11];
    const float* w2         = (const float*)d_in[12];
    float* out = (float*)d_out;

    float *p_xn, *p_xr, *p_u, *p_xdbl, *p_xp, *p_delta, *p_xm2, *p_xm2n, *p_y2, *p_tv, *p_pw;
    int *p_te, *p_off, *p_ptok, *p_tp;
    cudaGetSymbolAddress((void**)&p_xn, g_xn);
    cudaGetSymbolAddress((void**)&p_xr, g_xr);
    cudaGetSymbolAddress((void**)&p_u, g_u);
    cudaGetSymbolAddress((void**)&p_xdbl, g_xdbl);
    cudaGetSymbolAddress((void**)&p_xp, g_xp);
    cudaGetSymbolAddress((void**)&p_delta, g_delta);
    cudaGetSymbolAddress((void**)&p_xm2, g_xm2);
    cudaGetSymbolAddress((void**)&p_xm2n, g_xm2n);
    cudaGetSymbolAddress((void**)&p_y2, g_y2);
    cudaGetSymbolAddress((void**)&p_te, g_top_e);
    cudaGetSymbolAddress((void**)&p_tv, g_top_v);
    cudaGetSymbolAddress((void**)&p_off, g_off);
    cudaGetSymbolAddress((void**)&p_ptok, g_ptok);
    cudaGetSymbolAddress((void**)&p_pw, g_pw);
    cudaGetSymbolAddress((void**)&p_tp, g_tok_pair);

    __half *xnh, *xdh, *yh, *x2h, *hh, *wih, *wdh, *woh;
    cudaGetSymbolAddress((void**)&xnh, h_xn);
    cudaGetSymbolAddress((void**)&xdh, h_xd);
    cudaGetSymbolAddress((void**)&yh,  h_y);
    cudaGetSymbolAddress((void**)&x2h, h_x2);
    cudaGetSymbolAddress((void**)&hh,  h_h);
    cudaGetSymbolAddress((void**)&wih, h_wi);
    cudaGetSymbolAddress((void**)&wdh, h_wd);
    cudaGetSymbolAddress((void**)&woh, h_wo);

    const int SMEM = NSTG * STG_B;   // 48 KB
    cudaFuncSetAttribute((const void*)hgemm<0, 0, 0>, cudaFuncAttributeMaxDynamicSharedMemorySize, SMEM);
    cudaFuncSetAttribute((const void*)hgemm<3, 0, 0>, cudaFuncAttributeMaxDynamicSharedMemorySize, SMEM);
    cudaFuncSetAttribute((const void*)hgemm<2, 0, 0>, cudaFuncAttributeMaxDynamicSharedMemorySize, SMEM);
    cudaFuncSetAttribute((const void*)hgemm<1, 1, 1>, cudaFuncAttributeMaxDynamicSharedMemorySize, SMEM);
    cudaFuncSetAttribute((const void*)hgemm<0, 2, 1>, cudaFuncAttributeMaxDynamicSharedMemorySize, SMEM);

    // 0. convert small weights to fp16 (w1/w2 converted in-GEMM)
    conv_h<<<(2 * DINNER * DMODEL / 4 + 255) / 256, 256>>>((const float4*)in_proj_w, (uint2*)wih, 2 * DINNER * DMODEL / 4);
    conv_h<<<(DINNER * DTRANK / 4 + 255) / 256, 256>>>((const float4*)dt_proj_w, (uint2*)wdh, DINNER * DTRANK / 4);
    conv_h<<<(DMODEL * DINNER / 4 + 255) / 256, 256>>>((const float4*)out_proj_w, (uint2*)woh, DMODEL * DINNER / 4);

    // 1. xn = rmsnorm(x)
    rmsnorm_h<<<LSEQ, 256>>>(x, p_xn, xnh);
    // 2. xr = xn @ in_proj^T (2048x4096, K=1024)
    hgemm<0, 0, 0><<<dim3(16, 32), 256, SMEM>>>(xnh, DMODEL, wih, nullptr, DMODEL,
                                                p_xr, 2 * DINNER, LSEQ, 2 * DINNER,
                                                nullptr, nullptr, 0, nullptr, nullptr, nullptr);
    // 3. conv + silu
    conv_silu<<<(LSEQ * DINNER) / 256, 256>>>(p_xr, conv_w, conv_b, p_u);
    // 4. x_dbl = u @ x_proj^T (2048x96, K=2048) split-K=16 exact fp32
    gemm_sk<<<dim3(32, 2, SPLITK), 256>>>(p_u, DINNER, x_proj_w, DINNER,
                                          p_xp, XDBL, LSEQ, XDBL, DINNER / SPLITK);
    reduce_sk<<<(LSEQ * XDBL + 255) / 256, 256>>>(p_xp, p_xdbl, xdh, LSEQ * XDBL);
    // 5. delta = softplus(dt @ dt_proj^T + b) (2048x2048, K=64)
    hgemm<3, 0, 0><<<dim3(16, 16), 256, SMEM>>>(xdh, XDBL, wdh, nullptr, DTRANK,
                                                p_delta, DINNER, LSEQ, DINNER,
                                                dt_proj_b, nullptr, 0, nullptr, nullptr, nullptr);
    // 6. selective scan -> y fp16
    scan_kernel<<<DINNER / 8, 128>>>(p_delta, p_u, p_xdbl, A_log, Dvec, p_xr, yh);
    // 7. xm2 = y @ out_proj^T + xn (2048x1024, K=2048)
    hgemm<2, 0, 0><<<dim3(16, 8), 256, SMEM>>>(yh, DINNER, woh, nullptr, DINNER,
                                               p_xm2, DMODEL, LSEQ, DMODEL,
                                               nullptr, p_xn, DMODEL, nullptr, nullptr, nullptr);
    // 8. xm2n = rmsnorm(xm2)
    rmsnorm_h<<<LSEQ, 256>>>(p_xm2, p_xm2n, x2h);
    // 9. gating + routing (fused)
    gate_topk<<<LSEQ / 4, 128>>>(p_xm2n, gate_w, p_te, p_tv);
    route_all<<<1, 256>>>(p_te, p_tv, p_off, p_ptok, p_pw, p_tp);
    // 10. expert GEMMs (fp32 weights, converted in-kernel)
    hgemm<1, 1, 1><<<dim3(32, 32, NEXP), 256, SMEM>>>(x2h, DMODEL, nullptr, w1, DMODEL,
                                                      nullptr, HIDDEN, 0, HIDDEN,
                                                      nullptr, nullptr, 0, p_off, p_ptok, hh);
    hgemm<0, 2, 1><<<dim3(32, 8, NEXP), 256, SMEM>>>(hh, HIDDEN, nullptr, w2, HIDDEN,
                                                     p_y2, DMODEL, 0, DMODEL,
                                                     nullptr, nullptr, 0, p_off, nullptr, nullptr);
    moe_combine<<<(LSEQ * DMODEL) / 256, 256>>>(x, p_y2, p_tp, p_pw, out);
}

// round 15
// speedup vs baseline: 1.5980x; 1.5619x over previous
#include <cuda_runtime.h>
#include <cuda_fp16.h>
#include <math.h>
#include <stdint.h>

// ---------------- problem constants ----------------
#define LSEQ   2048
#define DMODEL 1024
#define DINNER 2048
#define DSTATE 16
#define DTRANK 64
#define XDBL   96
#define NEXP   8
#define HIDDEN 4096
#define NPAIR  4096
#define SPLITK 16
#define NCHUNK 16
#define CLEN   128   // LSEQ / NCHUNK

// ---------------- fp32 scratch ----------------
__device__ float g_xn   [LSEQ * DMODEL];
__device__ float g_xr   [LSEQ * 2 * DINNER];
__device__ float g_u    [LSEQ * DINNER];
__device__ float g_xdbl [LSEQ * XDBL];
__device__ float g_xp   [SPLITK * LSEQ * XDBL];
__device__ float g_delta[LSEQ * DINNER];
__device__ float g_xm2  [LSEQ * DMODEL];
__device__ float g_xm2n [LSEQ * DMODEL];
__device__ float g_y2   [(size_t)NPAIR * DMODEL];
__device__ float g_Hc   [NCHUNK * DINNER * DSTATE];
__device__ float g_Wc   [NCHUNK * DINNER * DSTATE];
__device__ float g_h0   [NCHUNK * DINNER * DSTATE];
__device__ int   g_top_e[LSEQ * 2];
__device__ float g_top_v[LSEQ * 2];
__device__ int   g_off[NEXP + 1];
__device__ int   g_ptok[NPAIR];
__device__ float g_pw  [NPAIR];
__device__ int   g_tok_pair[LSEQ * 2];

// ---------------- fp16 scratch ----------------
__device__ __align__(16) __half h_xn [LSEQ * DMODEL];
__device__ __align__(16) __half h_xd [LSEQ * XDBL];
__device__ __align__(16) __half h_y  [LSEQ * DINNER];
__device__ __align__(16) __half h_x2 [LSEQ * DMODEL];
__device__ __align__(16) __half h_h  [(size_t)NPAIR * HIDDEN];
__device__ __align__(16) __half h_wi [2 * DINNER * DMODEL];
__device__ __align__(16) __half h_wd [DINNER * DTRANK];
__device__ __align__(16) __half h_wo [DMODEL * DINNER];

// ---------------- helpers ----------------
__device__ __forceinline__ void cpa16(uint32_t dst, const void* src)
{
    asm volatile("cp.async.cg.shared.global [%0], [%1], 16;" :: "r"(dst), "l"(src));
}

__device__ __forceinline__ void ldsm4(uint32_t* r, uint32_t a)
{
    asm volatile("ldmatrix.sync.aligned.m8n8.x4.shared.b16 {%0,%1,%2,%3}, [%4];"
                 : "=r"(r[0]), "=r"(r[1]), "=r"(r[2]), "=r"(r[3]) : "r"(a));
}

__device__ __forceinline__ void hmma(float* d, const uint32_t* a, const uint32_t* b)
{
    asm volatile(
        "mma.sync.aligned.m16n8k16.row.col.f32.f16.f16.f32 "
        "{%0,%1,%2,%3},{%4,%5,%6,%7},{%8,%9},{%0,%1,%2,%3};\n"
        : "+f"(d[0]), "+f"(d[1]), "+f"(d[2]), "+f"(d[3])
        : "r"(a[0]), "r"(a[1]), "r"(a[2]), "r"(a[3]), "r"(b[0]), "r"(b[1]));
}

__device__ __forceinline__ uint2 cvt4(float4 v)
{
    __half2 h01 = __halves2half2(__float2half_rn(v.x), __float2half_rn(v.y));
    __half2 h23 = __halves2half2(__float2half_rn(v.z), __float2half_rn(v.w));
    return make_uint2(*(uint32_t*)&h01, *(uint32_t*)&h23);
}

__device__ __forceinline__ uint4 cvt8(float4 a, float4 b)
{
    uint2 lo = cvt4(a), hi = cvt4(b);
    return make_uint4(lo.x, lo.y, hi.x, hi.y);
}

// ---------------- weight convert: fp32 -> fp16 ----------------
__global__ void conv_h(const float4* __restrict__ src, uint2* __restrict__ dst, int n4)
{
    int i = blockIdx.x * 256 + threadIdx.x;
    if (i >= n4) return;
    dst[i] = cvt4(src[i]);
}

// ---------------- fp16 tensor GEMM: C = epi(A @ W^T) ----------------
#define NSTG 3
#define STG_B 16384
template<int EPI, int MODE, int BCVT>
__global__ void __launch_bounds__(256, 2) hgemm(
    const __half* __restrict__ Aq, int lda,
    const __half* __restrict__ Wq, const float* __restrict__ Wf, int K,
    float* __restrict__ C, int ldc, int M, int N,
    const float* __restrict__ bias, const float* __restrict__ addsrc, int ldadd,
    const int* __restrict__ off, const int* __restrict__ ptok,
    __half* __restrict__ Ch)
{
    extern __shared__ __align__(16) uint8_t smem[];
    int base = 0, rows = M;
    const __half* W = Wq;
    const float* WF = Wf;
    if (MODE != 0) {
        int e = blockIdx.z;
        base = off[e];
        rows = off[e + 1] - base;
        if (BCVT) WF += (size_t)e * (size_t)N * K;
        else      W  += (size_t)e * (size_t)N * K;
    }
    int m0 = blockIdx.x * 128;
    if (m0 >= rows) return;
    int n0 = blockIdx.y * 128;

    int tid = threadIdx.x;
    int wid = tid >> 5, lane = tid & 31;
    int lr = lane >> 2, lc = lane & 3;
    int warp_m = wid >> 2, warp_n = wid & 3;

    int qg = tid & 3;
    int ar = tid >> 2;
    int rA0 = m0 + ar, rA1 = rA0 + 64;
    int c0 = rA0 < rows ? rA0 : rows - 1;
    int c1 = rA1 < rows ? rA1 : rows - 1;
    int gA0, gA1;
    if (MODE == 1)      { gA0 = ptok[base + c0]; gA1 = ptok[base + c1]; }
    else if (MODE == 2) { gA0 = base + c0;       gA1 = base + c1; }
    else                { gA0 = c0;              gA1 = c1; }

    const __half* pA0 = Aq + (size_t)gA0 * lda + qg * 8;
    const __half* pA1 = Aq + (size_t)gA1 * lda + qg * 8;
    const __half* pB0h = BCVT ? nullptr : (W + (size_t)(n0 + ar) * K + qg * 8);
    const __half* pB1h = BCVT ? nullptr : (W + (size_t)(n0 + ar + 64) * K + qg * 8);
    const float*  pB0f = BCVT ? (WF + (size_t)(n0 + ar) * K + qg * 8) : nullptr;
    const float*  pB1f = BCVT ? (WF + (size_t)(n0 + ar + 64) * K + qg * 8) : nullptr;

    uint32_t sb0 = (uint32_t)__cvta_generic_to_shared(smem);
    int dst0 = ar * 64 + ((qg ^ ((ar >> 1) & 3)) << 4);
    int dst1 = dst0 + 4096;

    int rA = warp_m * 64 + (lane & 15);
    int swzA = (rA >> 1) & 3;
    int aoff0 = rA * 64 + ((((lane >> 4)) ^ swzA) << 4);
    int aoff1 = rA * 64 + (((2 + (lane >> 4)) ^ swzA) << 4);
    int rB = warp_n * 32 + (lane & 7) + ((lane >> 4) << 3);
    int swzB = (rB >> 1) & 3;
    int boff0 = rB * 64 + ((((lane >> 3) & 1) ^ swzB) << 4);
    int boff1 = rB * 64 + (((2 + ((lane >> 3) & 1)) ^ swzB) << 4);

    float acc[4][4][4];
    #pragma unroll
    for (int i = 0; i < 4; i++)
        #pragma unroll
        for (int j = 0; j < 4; j++)
            #pragma unroll
            for (int r = 0; r < 4; r++) acc[i][j][r] = 0.f;

    int nt = K >> 5;
    float4 br[4];
    if (BCVT) {
        br[0] = __ldg((const float4*)pB0f);
        br[1] = __ldg((const float4*)(pB0f + 4));
        br[2] = __ldg((const float4*)pB1f);
        br[3] = __ldg((const float4*)(pB1f + 4));
        *(uint4*)(smem + 8192 + dst0) = cvt8(br[0], br[1]);
        *(uint4*)(smem + 8192 + dst1) = cvt8(br[2], br[3]);
        cpa16(sb0 + dst0, pA0);
        cpa16(sb0 + dst1, pA1);
        asm volatile("cp.async.commit_group;");
        if (nt > 1) {
            br[0] = __ldg((const float4*)(pB0f + 32));
            br[1] = __ldg((const float4*)(pB0f + 36));
            br[2] = __ldg((const float4*)(pB1f + 32));
            br[3] = __ldg((const float4*)(pB1f + 36));
            uint32_t s = sb0 + STG_B;
            cpa16(s + dst0, pA0 + 32);
            cpa16(s + dst1, pA1 + 32);
        }
        asm volatile("cp.async.commit_group;");
    } else {
        cpa16(sb0 + 0    + dst0, pA0);
        cpa16(sb0 + 0    + dst1, pA1);
        cpa16(sb0 + 8192 + dst0, pB0h);
        cpa16(sb0 + 8192 + dst1, pB1h);
        asm volatile("cp.async.commit_group;");
        if (nt > 1) {
            uint32_t s = sb0 + STG_B;
            cpa16(s + 0    + dst0, pA0 + 32);
            cpa16(s + 0    + dst1, pA1 + 32);
            cpa16(s + 8192 + dst0, pB0h + 32);
            cpa16(s + 8192 + dst1, pB1h + 32);
        }
        asm volatile("cp.async.commit_group;");
    }
    int buf = 0;
    for (int t = 0; t < nt; t++) {
        asm volatile("cp.async.wait_group 1;");
        __syncthreads();
        if (BCVT) {
            if (t + 1 < nt) {
                int nb1 = buf + 1; if (nb1 >= NSTG) nb1 -= NSTG;
                *(uint4*)(smem + nb1 * STG_B + 8192 + dst0) = cvt8(br[0], br[1]);
                *(uint4*)(smem + nb1 * STG_B + 8192 + dst1) = cvt8(br[2], br[3]);
            }
            if (t + 2 < nt) {
                int kc = (t + 2) << 5;
                br[0] = __ldg((const float4*)(pB0f + kc));
                br[1] = __ldg((const float4*)(pB0f + kc + 4));
                br[2] = __ldg((const float4*)(pB1f + kc));
                br[3] = __ldg((const float4*)(pB1f + kc + 4));
                int nb = buf + 2; if (nb >= NSTG) nb -= NSTG;
                uint32_t s = sb0 + nb * STG_B;
                cpa16(s + dst0, pA0 + kc);
                cpa16(s + dst1, pA1 + kc);
            }
        } else if (t + 2 < nt) {
            int kc = (t + 2) << 5;
            int nb = buf + 2; if (nb >= NSTG) nb -= NSTG;
            uint32_t s = sb0 + nb * STG_B;
            cpa16(s + 0    + dst0, pA0 + kc);
            cpa16(s + 0    + dst1, pA1 + kc);
            cpa16(s + 8192 + dst0, pB0h + kc);
            cpa16(s + 8192 + dst1, pB1h + kc);
        }
        asm volatile("cp.async.commit_group;");

        uint32_t S = sb0 + buf * STG_B;
        #pragma unroll
        for (int sub = 0; sub < 2; sub++) {
            uint32_t aadr = S + (sub ? aoff1 : aoff0);
            uint32_t badr = S + 8192 + (sub ? boff1 : boff0);
            uint32_t ah[4][4];
            #pragma unroll
            for (int im = 0; im < 4; im++) ldsm4(ah[im], aadr + im * 1024);
            uint32_t b0[4], b1[4];
            ldsm4(b0, badr);
            ldsm4(b1, badr + 1024);
            #pragma unroll
            for (int im = 0; im < 4; im++) {
                hmma(acc[im][0], ah[im], b0);
                hmma(acc[im][1], ah[im], b0 + 2);
                hmma(acc[im][2], ah[im], b1);
                hmma(acc[im][3], ah[im], b1 + 2);
            }
        }
        if (++buf == NSTG) buf = 0;
    }

    #pragma unroll
    for (int im = 0; im < 4; im++) {
        #pragma unroll
        for (int half = 0; half < 2; half++) {
            int m = m0 + warp_m * 64 + im * 16 + lr + half * 8;
            if (m >= rows) continue;
            size_t crow = (size_t)(base + m) * (size_t)ldc;
            if (MODE == 0) crow = (size_t)m * ldc;
            #pragma unroll
            for (int in = 0; in < 4; in++) {
                int n = n0 + warp_n * 32 + in * 8 + lc * 2;
                float v0 = acc[im][in][half * 2];
                float v1 = acc[im][in][half * 2 + 1];
                if (EPI == 1) {
                    v0 = 0.5f * v0 * (1.0f + erff(v0 * 0.70710678118654752f));
                    v1 = 0.5f * v1 * (1.0f + erff(v1 * 0.70710678118654752f));
                    __half2 hv = __halves2half2(__float2half_rn(v0), __float2half_rn(v1));
                    *(__half2*)(Ch + crow + n) = hv;
                } else {
                    if (EPI == 2) {
                        v0 += addsrc[(size_t)m * ldadd + n];
                        v1 += addsrc[(size_t)m * ldadd + n + 1];
                    } else if (EPI == 3) {
                        float z0 = v0 + bias[n], z1 = v1 + bias[n + 1];
                        v0 = (z0 > 20.f) ? z0 : log1pf(__expf(z0));
                        v1 = (z1 > 20.f) ? z1 : log1pf(__expf(z1));
                    }
                    *(float2*)(C + crow + n) = make_float2(v0, v1);
                }
            }
        }
    }
}

// ---------------- rmsnorm (writes fp32 + fp16) ----------------
__global__ void rmsnorm_h(const float* __restrict__ x, float* __restrict__ o,
                          __half* __restrict__ oh)
{
    int row = blockIdx.x;
    const float4* xp = (const float4*)(x + (size_t)row * DMODEL);
    float4 v = xp[threadIdx.x];
    float s = v.x * v.x + v.y * v.y + v.z * v.z + v.w * v.w;
    __shared__ float ssum[8];
    #pragma unroll
    for (int off = 16; off; off >>= 1) s += __shfl_xor_sync(0xffffffffu, s, off);
    if ((threadIdx.x & 31) == 0) ssum[threadIdx.x >> 5] = s;
    __syncthreads();
    if (threadIdx.x < 8) {
        float t = ssum[threadIdx.x];
        #pragma unroll
        for (int off = 4; off; off >>= 1) t += __shfl_xor_sync(0xffu, t, off);
        if (threadIdx.x == 0) ssum[0] = t;
    }
    __syncthreads();
    float scale = 32.0f / fmaxf(sqrtf(ssum[0]), 1e-12f);
    float4 w = make_float4(v.x * scale, v.y * scale, v.z * scale, v.w * scale);
    ((float4*)(o + (size_t)row * DMODEL))[threadIdx.x] = w;
    ((uint2*)(oh + (size_t)row * DMODEL))[threadIdx.x] = cvt4(w);
}

// ---------------- split-K SIMT GEMM for skinny x_proj (exact fp32) ----------------
__global__ void __launch_bounds__(256) gemm_sk(
    const float* __restrict__ A, int lda,
    const float* __restrict__ W, int ldw,
    float* __restrict__ Cpart, int ldc,
    int M, int N, int kchunk)
{
    int koff = blockIdx.z * kchunk;
    float* C = Cpart + (size_t)blockIdx.z * M * ldc;
    __shared__ float As[16][68];
    __shared__ float Bs[16][68];
    int tid = threadIdx.x;
    int m0 = blockIdx.x * 64, n0 = blockIdx.y * 64;
    int tx = tid & 15, ty = tid >> 4;
    int lr = tid >> 2;
    int lk = (tid & 3) << 2;
    int am = m0 + lr;
    int wn = n0 + lr;
    bool a_ok = am < M;
    bool w_ok = wn < N;
    const float* Arow = A + (size_t)(a_ok ? am : 0) * lda + koff;
    const float* Wrow = W + (size_t)(w_ok ? wn : 0) * ldw + koff;
    float acc[4][4] = {};
    for (int k0 = 0; k0 < kchunk; k0 += 16) {
        float4 av = a_ok ? *(const float4*)(Arow + k0 + lk) : make_float4(0, 0, 0, 0);
        float4 wv = w_ok ? *(const float4*)(Wrow + k0 + lk) : make_float4(0, 0, 0, 0);
        __syncthreads();
        As[lk][lr] = av.x; As[lk + 1][lr] = av.y; As[lk + 2][lr] = av.z; As[lk + 3][lr] = av.w;
        Bs[lk][lr] = wv.x; Bs[lk + 1][lr] = wv.y; Bs[lk + 2][lr] = wv.z; Bs[lk + 3][lr] = wv.w;
        __syncthreads();
        #pragma unroll
        for (int k = 0; k < 16; k++) {
            float a[4], b[4];
            #pragma unroll
            for (int i = 0; i < 4; i++) a[i] = As[k][ty * 4 + i];
            #pragma unroll
            for (int j = 0; j < 4; j++) b[j] = Bs[k][tx * 4 + j];
            #pragma unroll
            for (int i = 0; i < 4; i++)
                #pragma unroll
                for (int j = 0; j < 4; j++)
                    acc[i][j] += a[i] * b[j];
        }
    }
    #pragma unroll
    for (int i = 0; i < 4; i++) {
        int m = m0 + ty * 4 + i;
        if (m >= M) continue;
        #pragma unroll
        for (int j = 0; j < 4; j++) {
            int n = n0 + tx * 4 + j;
            if (n >= N) continue;
            C[(size_t)m * ldc + n] = acc[i][j];
        }
    }
}

__global__ void reduce_sk(const float* __restrict__ p, float* __restrict__ o,
                          __half* __restrict__ oh, int n)
{
    int i = blockIdx.x * 256 + threadIdx.x;
    if (i >= n) return;
    float s = 0.f;
    #pragma unroll
    for (int j = 0; j < SPLITK; j++) s += p[i + (size_t)j * n];
    o[i] = s;
    oh[i] = __float2half_rn(s);
}

// ---------------- causal depthwise conv(4) + silu ----------------
__global__ void conv_silu(const float* __restrict__ xr, const float* __restrict__ cw,
                          const float* __restrict__ cb, float* __restrict__ u)
{
    int idx = blockIdx.x * 256 + threadIdx.x;
    int t = idx >> 11, d = idx & (DINNER - 1);
    float w0 = cw[d * 4], w1 = cw[d * 4 + 1], w2 = cw[d * 4 + 2], w3 = cw[d * 4 + 3];
    float s = cb[d];
    const float* col = xr + d;
    if (t >= 3) s += col[(size_t)(t - 3) * (2 * DINNER)] * w0;
    if (t >= 2) s += col[(size_t)(t - 2) * (2 * DINNER)] * w1;
    if (t >= 1) s += col[(size_t)(t - 1) * (2 * DINNER)] * w2;
    s += col[(size_t)t * (2 * DINNER)] * w3;
    u[idx] = s / (1.f + __expf(-s));
}

// ---------------- chunked selective scan ----------------
// phase A: per-chunk local scan (h0=0), store H_c and W_c (dA product)
__global__ void scan_part(const float* __restrict__ delta,
                          const float* __restrict__ u,
                          const float* __restrict__ xdbl,
                          const float* __restrict__ A_log,
                          float* __restrict__ Hc, float* __restrict__ Wc)
{
    int lane16 = threadIdx.x & 15;
    int ch = threadIdx.x >> 4;
    int d = blockIdx.x * 8 + ch;
    int c = blockIdx.y;
    float A = -__expf(A_log[d * DSTATE + lane16]);
    float h = 0.f, Wp = 1.f;
    __shared__ float sB[32][16], sdl[32][8], su[32][8];
    for (int t0 = c * CLEN; t0 < (c + 1) * CLEN; t0 += 32) {
        __syncthreads();
        for (int i = threadIdx.x; i < 512; i += 128) {
            int tt = i >> 4, n = i & 15;
            sB[tt][n] = xdbl[(size_t)(t0 + tt) * XDBL + DTRANK + n];
        }
        for (int i = threadIdx.x; i < 256; i += 128) {
            int tt = i >> 3, cc = i & 7;
            size_t off = (size_t)(t0 + tt) * DINNER + blockIdx.x * 8 + cc;
            sdl[tt][cc] = delta[off];
            su[tt][cc]  = u[off];
        }
        __syncthreads();
        for (int tt = 0; tt < 32; tt++) {
            float dl = sdl[tt][ch];
            float dA = __expf(dl * A);
            h = dA * h + dl * sB[tt][lane16] * su[tt][ch];
            Wp *= dA;
        }
    }
    int idx = (c * DINNER + d) * DSTATE + lane16;
    Hc[idx] = h;
    Wc[idx] = Wp;
}

// phase B: sequential fix-up over 16 chunks per (d,n); writes chunk-entry states
__global__ void scan_fix(const float* __restrict__ Hc, const float* __restrict__ Wc,
                         float* __restrict__ h0)
{
    int idx = blockIdx.x * 256 + threadIdx.x;   // over DINNER*DSTATE
    float h = 0.f;
    #pragma unroll
    for (int c = 0; c < NCHUNK; c++) {
        int o = c * DINNER * DSTATE + idx;
        h0[o] = h;
        h = Wc[o] * h + Hc[o];
    }
}

// phase C: rerun chunk from true entry state, emit y (fp16, with D and silu(res))
__global__ void scan_final(const float* __restrict__ delta,
                           const float* __restrict__ u,
                           const float* __restrict__ xdbl,
                           const float* __restrict__ A_log,
                           const float* __restrict__ Dvec,
                           const float* __restrict__ xr,
                           const float* __restrict__ h0,
                           __half* __restrict__ yh)
{
    int lane16 = threadIdx.x & 15;
    int ch = threadIdx.x >> 4;
    int d = blockIdx.x * 8 + ch;
    int c = blockIdx.y;
    float A = -__expf(A_log[d * DSTATE + lane16]);
    float Dd = Dvec[d];
    float h = h0[(c * DINNER + d) * DSTATE + lane16];
    __shared__ float sB[32][16], sC[32][16], sdl[32][8], su[32][8], sre[32][8];
    for (int t0 = c * CLEN; t0 < (c + 1) * CLEN; t0 += 32) {
        __syncthreads();
        for (int i = threadIdx.x; i < 512; i += 128) {
            int tt = i >> 4, n = i & 15;
            const float* xb = xdbl + (size_t)(t0 + tt) * XDBL;
            sB[tt][n] = xb[DTRANK + n];
            sC[tt][n] = xb[DTRANK + DSTATE + n];
        }
        for (int i = threadIdx.x; i < 256; i += 128) {
            int tt = i >> 3, cc = i & 7;
            int dd = blockIdx.x * 8 + cc;
            size_t off = (size_t)(t0 + tt) * DINNER + dd;
            sdl[tt][cc] = delta[off];
            su[tt][cc]  = u[off];
            sre[tt][cc] = xr[(size_t)(t0 + tt) * (2 * DINNER) + DINNER + dd];
        }
        __syncthreads();
        for (int tt = 0; tt < 32; tt++) {
            float dl = sdl[tt][ch];
            float uu = su[tt][ch];
            float dA = __expf(dl * A);
            h = dA * h + dl * sB[tt][lane16] * uu;
            float p = h * sC[tt][lane16];
            #pragma unroll
            for (int o = 8; o; o >>= 1) p += __shfl_xor_sync(0xffffffffu, p, o, 16);
            if (lane16 == 0) {
                float yv = p + uu * Dd;
                float r = sre[tt][ch];
                yv *= r / (1.f + __expf(-r));
                yh[(size_t)(t0 + tt) * DINNER + d] = __float2half_rn(yv);
            }
        }
    }
}

// ---------------- gating: GEMV + softmax + top-2 ----------------
__global__ void gate_topk(const float* __restrict__ X, const float* __restrict__ gw,
                          int* __restrict__ te, float* __restrict__ tv)
{
    __shared__ float sg[NEXP * DMODEL];
    for (int i = threadIdx.x; i < NEXP * DMODEL; i += 128) sg[i] = gw[i];
    __syncthreads();
    int warp = threadIdx.x >> 5, lane = threadIdx.x & 31;
    int t = blockIdx.x * 4 + warp;
    const float* xp = X + (size_t)t * DMODEL;
    float acc[NEXP] = {};
    for (int k = lane; k < DMODEL; k += 32) {
        float xv = xp[k];
        #pragma unroll
        for (int e = 0; e < NEXP; e++) acc[e] += xv * sg[e * DMODEL + k];
    }
    #pragma unroll
    for (int e = 0; e < NEXP; e++)
        #pragma unroll
        for (int o = 16; o; o >>= 1) acc[e] += __shfl_xor_sync(0xffffffffu, acc[e], o);
    if (lane == 0) {
        float m = acc[0];
        #pragma unroll
        for (int e = 1; e < NEXP; e++) m = fmaxf(m, acc[e]);
        float g[NEXP];
        #pragma unroll
        for (int e = 0; e < NEXP; e++) g[e] = __expf(acc[e] - m);
        int i0 = 0;
        #pragma unroll
        for (int e = 1; e < NEXP; e++) if (g[e] > g[i0]) i0 = e;
        int i1 = (i0 == 0) ? 1 : 0;
        #pragma unroll
        for (int e = 0; e < NEXP; e++) if (e != i0 && g[e] > g[i1]) i1 = e;
        float inv = 1.f / (g[i0] + g[i1]);
        te[t * 2] = i0; te[t * 2 + 1] = i1;
        tv[t * 2] = g[i0] * inv; tv[t * 2 + 1] = g[i1] * inv;
    }
}

// ---------------- fused routing (1 CTA) ----------------
__global__ void __launch_bounds__(256) route_all(
    const int* __restrict__ te, const float* __restrict__ tv,
    int* __restrict__ off, int* __restrict__ ptok, float* __restrict__ pw,
    int* __restrict__ tok_pair)
{
    __shared__ int scnt[NEXP], soff[NEXP + 1], scur[NEXP];
    int tid = threadIdx.x;
    if (tid < NEXP) scnt[tid] = 0;
    __syncthreads();
    for (int t = tid; t < LSEQ; t += 256) {
        atomicAdd(&scnt[te[t * 2]], 1);
        atomicAdd(&scnt[te[t * 2 + 1]], 1);
    }
    __syncthreads();
    if (tid == 0) {
        int s = 0;
        #pragma unroll
        for (int e = 0; e < NEXP; e++) { soff[e] = s; scur[e] = 0; s += scnt[e]; }
        soff[NEXP] = s;
    }
    __syncthreads();
    if (tid < NEXP + 1) off[tid] = soff[tid];
    for (int t = tid; t < LSEQ; t += 256) {
        #pragma unroll
        for (int k = 0; k < 2; k++) {
            int e = te[t * 2 + k];
            int pos = atomicAdd(&scur[e], 1);
            int p = soff[e] + pos;
            ptok[p] = t;
            pw[p] = tv[t * 2 + k];
            tok_pair[t * 2 + k] = p;
        }
    }
}

// ---------------- final combine ----------------
__global__ void moe_combine(const float* __restrict__ x, const float* __restrict__ y2,
                            const int* __restrict__ tok_pair, const float* __restrict__ pw,
                            float* __restrict__ out)
{
    int i = blockIdx.x * 256 + threadIdx.x;
    int t = i >> 10, n = i & (DMODEL - 1);
    int p0 = tok_pair[t * 2], p1 = tok_pair[t * 2 + 1];
    out[i] = x[i] + pw[p0] * y2[(size_t)p0 * DMODEL + n]
                  + pw[p1] * y2[(size_t)p1 * DMODEL + n];
}

// ---------------- launch ----------------
extern "C" void kernel_launch(void* const* d_in, const int* in_sizes, int n_in,
                              void* d_out, int out_size)
{
    (void)in_sizes; (void)n_in; (void)out_size;
    const float* x          = (const float*)d_in[0];
    const float* in_proj_w  = (const float*)d_in[1];
    const float* conv_w     = (const float*)d_in[2];
    const float* conv_b     = (const float*)d_in[3];
    const float* x_proj_w   = (const float*)d_in[4];
    const float* dt_proj_w  = (const float*)d_in[5];
    const float* dt_proj_b  = (const float*)d_in[6];
    const float* A_log      = (const float*)d_in[7];
    const float* Dvec       = (const float*)d_in[8];
    const float* out_proj_w = (const float*)d_in[9];
    const float* gate_w     = (const float*)d_in[10];
    const float* w1         = (const float*)d_in[11];
    const float* w2         = (const float*)d_in[12];
    float* out = (float*)d_out;

    float *p_xn, *p_xr, *p_u, *p_xdbl, *p_xp, *p_delta, *p_xm2, *p_xm2n, *p_y2, *p_tv, *p_pw;
    float *p_Hc, *p_Wc, *p_h0;
    int *p_te, *p_off, *p_ptok, *p_tp;
    cudaGetSymbolAddress((void**)&p_xn, g_xn);
    cudaGetSymbolAddress((void**)&p_xr, g_xr);
    cudaGetSymbolAddress((void**)&p_u, g_u);
    cudaGetSymbolAddress((void**)&p_xdbl, g_xdbl);
    cudaGetSymbolAddress((void**)&p_xp, g_xp);
    cudaGetSymbolAddress((void**)&p_delta, g_delta);
    cudaGetSymbolAddress((void**)&p_xm2, g_xm2);
    cudaGetSymbolAddress((void**)&p_xm2n, g_xm2n);
    cudaGetSymbolAddress((void**)&p_y2, g_y2);
    cudaGetSymbolAddress((void**)&p_Hc, g_Hc);
    cudaGetSymbolAddress((void**)&p_Wc, g_Wc);
    cudaGetSymbolAddress((void**)&p_h0, g_h0);
    cudaGetSymbolAddress((void**)&p_te, g_top_e);
    cudaGetSymbolAddress((void**)&p_tv, g_top_v);
    cudaGetSymbolAddress((void**)&p_off, g_off);
    cudaGetSymbolAddress((void**)&p_ptok, g_ptok);
    cudaGetSymbolAddress((void**)&p_pw, g_pw);
    cudaGetSymbolAddress((void**)&p_tp, g_tok_pair);

    __half *xnh, *xdh, *yh, *x2h, *hh, *wih, *wdh, *woh;
    cudaGetSymbolAddress((void**)&xnh, h_xn);
    cudaGetSymbolAddress((void**)&xdh, h_xd);
    cudaGetSymbolAddress((void**)&yh,  h_y);
    cudaGetSymbolAddress((void**)&x2h, h_x2);
    cudaGetSymbolAddress((void**)&hh,  h_h);
    cudaGetSymbolAddress((void**)&wih, h_wi);
    cudaGetSymbolAddress((void**)&wdh, h_wd);
    cudaGetSymbolAddress((void**)&woh, h_wo);

    const int SMEM = NSTG * STG_B;   // 48 KB
    cudaFuncSetAttribute((const void*)hgemm<0, 0, 0>, cudaFuncAttributeMaxDynamicSharedMemorySize, SMEM);
    cudaFuncSetAttribute((const void*)hgemm<3, 0, 0>, cudaFuncAttributeMaxDynamicSharedMemorySize, SMEM);
    cudaFuncSetAttribute((const void*)hgemm<2, 0, 0>, cudaFuncAttributeMaxDynamicSharedMemorySize, SMEM);
    cudaFuncSetAttribute((const void*)hgemm<1, 1, 1>, cudaFuncAttributeMaxDynamicSharedMemorySize, SMEM);
    cudaFuncSetAttribute((const void*)hgemm<0, 2, 1>, cudaFuncAttributeMaxDynamicSharedMemorySize, SMEM);

    // 0. convert small weights to fp16 (w1/w2 converted in-GEMM)
    conv_h<<<(2 * DINNER * DMODEL / 4 + 255) / 256, 256>>>((const float4*)in_proj_w, (uint2*)wih, 2 * DINNER * DMODEL / 4);
    conv_h<<<(DINNER * DTRANK / 4 + 255) / 256, 256>>>((const float4*)dt_proj_w, (uint2*)wdh, DINNER * DTRANK / 4);
    conv_h<<<(DMODEL * DINNER / 4 + 255) / 256, 256>>>((const float4*)out_proj_w, (uint2*)woh, DMODEL * DINNER / 4);

    // 1. xn = rmsnorm(x)
    rmsnorm_h<<<LSEQ, 256>>>(x, p_xn, xnh);
    // 2. xr = xn @ in_proj^T
    hgemm<0, 0, 0><<<dim3(16, 32), 256, SMEM>>>(xnh, DMODEL, wih, nullptr, DMODEL,
                                                p_xr, 2 * DINNER, LSEQ, 2 * DINNER,
                                                nullptr, nullptr, 0, nullptr, nullptr, nullptr);
    // 3. conv + silu
    conv_silu<<<(LSEQ * DINNER) / 256, 256>>>(p_xr, conv_w, conv_b, p_u);
    // 4. x_dbl = u @ x_proj^T (split-K exact fp32)
    gemm_sk<<<dim3(32, 2, SPLITK), 256>>>(p_u, DINNER, x_proj_w, DINNER,
                                          p_xp, XDBL, LSEQ, XDBL, DINNER / SPLITK);
    reduce_sk<<<(LSEQ * XDBL + 255) / 256, 256>>>(p_xp, p_xdbl, xdh, LSEQ * XDBL);
    // 5. delta = softplus(dt @ dt_proj^T + b)
    hgemm<3, 0, 0><<<dim3(16, 16), 256, SMEM>>>(xdh, XDBL, wdh, nullptr, DTRANK,
                                                p_delta, DINNER, LSEQ, DINNER,
                                                dt_proj_b, nullptr, 0, nullptr, nullptr, nullptr);
    // 6. chunked selective scan -> y fp16
    scan_part<<<dim3(DINNER / 8, NCHUNK), 128>>>(p_delta, p_u, p_xdbl, A_log, p_Hc, p_Wc);
    scan_fix<<<DINNER * DSTATE / 256, 256>>>(p_Hc, p_Wc, p_h0);
    scan_final<<<dim3(DINNER / 8, NCHUNK), 128>>>(p_delta, p_u, p_xdbl, A_log, Dvec,
                                                  p_xr, p_h0, yh);
    // 7. xm2 = y @ out_proj^T + xn
    hgemm<2, 0, 0><<<dim3(16, 8), 256, SMEM>>>(yh, DINNER, woh, nullptr, DINNER,
                                               p_xm2, DMODEL, LSEQ, DMODEL,
                                               nullptr, p_xn, DMODEL, nullptr, nullptr, nullptr);
    // 8. xm2n = rmsnorm(xm2)
    rmsnorm_h<<<LSEQ, 256>>>(p_xm2, p_xm2n, x2h);
    // 9. gating + routing (fused)
    gate_topk<<<LSEQ / 4, 128>>>(p_xm2n, gate_w, p_te, p_tv);
    route_all<<<1, 256>>>(p_te, p_tv, p_off, p_ptok, p_pw, p_tp);
    // 10. expert GEMMs (fp32 weights, converted in-kernel)
    hgemm<1, 1, 1><<<dim3(32, 32, NEXP), 256, SMEM>>>(x2h, DMODEL, nullptr, w1, DMODEL,
                                                      nullptr, HIDDEN, 0, HIDDEN,
                                                      nullptr, nullptr, 0, p_off, p_ptok, hh);
    hgemm<0, 2, 1><<<dim3(32, 8, NEXP), 256, SMEM>>>(hh, HIDDEN, nullptr, w2, HIDDEN,
                                                     p_y2, DMODEL, 0, DMODEL,
                                                     nullptr, nullptr, 0, p_off, nullptr, nullptr);
    moe_combine<<<(LSEQ * DMODEL) / 256, 256>>>(x, p_y2, p_tp, p_pw, out);
}

// round 16
// speedup vs baseline: 1.6310x; 1.0206x over previous
#include <cuda_runtime.h>
#include <cuda_fp16.h>
#include <math.h>
#include <stdint.h>

// ---------------- problem constants ----------------
#define LSEQ   2048
#define DMODEL 1024
#define DINNER 2048
#define DSTATE 16
#define DTRANK 64
#define XDBL   96
#define NEXP   8
#define HIDDEN 4096
#define NPAIR  4096
#define SPLITK 16
#define NCHUNK 16
#define CLEN   128   // LSEQ / NCHUNK

// ---------------- fp32 scratch ----------------
__device__ float g_xn   [LSEQ * DMODEL];
__device__ float g_xr   [LSEQ * 2 * DINNER];
__device__ float g_u    [LSEQ * DINNER];
__device__ float g_xdbl [LSEQ * XDBL];
__device__ float g_xp   [SPLITK * LSEQ * XDBL];
__device__ float g_delta[LSEQ * DINNER];
__device__ float g_xm2  [LSEQ * DMODEL];
__device__ float g_xm2n [LSEQ * DMODEL];
__device__ float g_y2   [(size_t)NPAIR * DMODEL];
__device__ float g_Hc   [NCHUNK * DINNER * DSTATE];
__device__ float g_Wc   [NCHUNK * DINNER * DSTATE];
__device__ float g_h0   [NCHUNK * DINNER * DSTATE];
__device__ int   g_top_e[LSEQ * 2];
__device__ float g_top_v[LSEQ * 2];
__device__ int   g_off[NEXP + 1];
__device__ int   g_ptok[NPAIR];
__device__ float g_pw  [NPAIR];
__device__ int   g_tok_pair[LSEQ * 2];

// ---------------- fp16 scratch ----------------
__device__ __align__(16) __half h_xn [LSEQ * DMODEL];
__device__ __align__(16) __half h_xd [LSEQ * XDBL];
__device__ __align__(16) __half h_y  [LSEQ * DINNER];
__device__ __align__(16) __half h_x2 [LSEQ * DMODEL];
__device__ __align__(16) __half h_h  [(size_t)NPAIR * HIDDEN];
__device__ __align__(16) __half h_wi [2 * DINNER * DMODEL];
__device__ __align__(16) __half h_wd [DINNER * DTRANK];
__device__ __align__(16) __half h_wo [DMODEL * DINNER];

// ---------------- helpers ----------------
__device__ __forceinline__ void cpa16(uint32_t dst, const void* src)
{
    asm volatile("cp.async.cg.shared.global [%0], [%1], 16;" :: "r"(dst), "l"(src));
}

__device__ __forceinline__ void ldsm4(uint32_t* r, uint32_t a)
{
    asm volatile("ldmatrix.sync.aligned.m8n8.x4.shared.b16 {%0,%1,%2,%3}, [%4];"
                 : "=r"(r[0]), "=r"(r[1]), "=r"(r[2]), "=r"(r[3]) : "r"(a));
}

__device__ __forceinline__ void hmma(float* d, const uint32_t* a, const uint32_t* b)
{
    asm volatile(
        "mma.sync.aligned.m16n8k16.row.col.f32.f16.f16.f32 "
        "{%0,%1,%2,%3},{%4,%5,%6,%7},{%8,%9},{%0,%1,%2,%3};\n"
        : "+f"(d[0]), "+f"(d[1]), "+f"(d[2]), "+f"(d[3])
        : "r"(a[0]), "r"(a[1]), "r"(a[2]), "r"(a[3]), "r"(b[0]), "r"(b[1]));
}

__device__ __forceinline__ uint2 cvt4(float4 v)
{
    __half2 h01 = __halves2half2(__float2half_rn(v.x), __float2half_rn(v.y));
    __half2 h23 = __halves2half2(__float2half_rn(v.z), __float2half_rn(v.w));
    return make_uint2(*(uint32_t*)&h01, *(uint32_t*)&h23);
}

__device__ __forceinline__ uint4 cvt8(float4 a, float4 b)
{
    uint2 lo = cvt4(a), hi = cvt4(b);
    return make_uint4(lo.x, lo.y, hi.x, hi.y);
}

// ---------------- weight convert: fp32 -> fp16 ----------------
__global__ void conv_h(const float4* __restrict__ src, uint2* __restrict__ dst, int n4)
{
    int i = blockIdx.x * 256 + threadIdx.x;
    if (i >= n4) return;
    dst[i] = cvt4(src[i]);
}

// ---------------- fp16 tensor GEMM: C = epi(A @ W^T) ----------------
#define NSTG 3
#define STG_B 16384
template<int EPI, int MODE, int BCVT>
__global__ void __launch_bounds__(256, 2) hgemm(
    const __half* __restrict__ Aq, int lda,
    const __half* __restrict__ Wq, const float* __restrict__ Wf, int K,
    float* __restrict__ C, int ldc, int M, int N,
    const float* __restrict__ bias, const float* __restrict__ addsrc, int ldadd,
    const int* __restrict__ off, const int* __restrict__ ptok,
    __half* __restrict__ Ch)
{
    extern __shared__ __align__(16) uint8_t smem[];
    int base = 0, rows = M;
    const __half* W = Wq;
    const float* WF = Wf;
    if (MODE != 0) {
        int e = blockIdx.z;
        base = off[e];
        rows = off[e + 1] - base;
        if (BCVT) WF += (size_t)e * (size_t)N * K;
        else      W  += (size_t)e * (size_t)N * K;
    }
    int m0 = blockIdx.x * 128;
    if (m0 >= rows) return;
    int n0 = blockIdx.y * 128;

    int tid = threadIdx.x;
    int wid = tid >> 5, lane = tid & 31;
    int lr = lane >> 2, lc = lane & 3;
    int warp_m = wid >> 2, warp_n = wid & 3;

    int qg = tid & 3;
    int ar = tid >> 2;
    int rA0 = m0 + ar, rA1 = rA0 + 64;
    int c0 = rA0 < rows ? rA0 : rows - 1;
    int c1 = rA1 < rows ? rA1 : rows - 1;
    int gA0, gA1;
    if (MODE == 1)      { gA0 = ptok[base + c0]; gA1 = ptok[base + c1]; }
    else if (MODE == 2) { gA0 = base + c0;       gA1 = base + c1; }
    else                { gA0 = c0;              gA1 = c1; }

    const __half* pA0 = Aq + (size_t)gA0 * lda + qg * 8;
    const __half* pA1 = Aq + (size_t)gA1 * lda + qg * 8;
    const __half* pB0h = BCVT ? nullptr : (W + (size_t)(n0 + ar) * K + qg * 8);
    const __half* pB1h = BCVT ? nullptr : (W + (size_t)(n0 + ar + 64) * K + qg * 8);
    const float*  pB0f = BCVT ? (WF + (size_t)(n0 + ar) * K + qg * 8) : nullptr;
    const float*  pB1f = BCVT ? (WF + (size_t)(n0 + ar + 64) * K + qg * 8) : nullptr;

    uint32_t sb0 = (uint32_t)__cvta_generic_to_shared(smem);
    int dst0 = ar * 64 + ((qg ^ ((ar >> 1) & 3)) << 4);
    int dst1 = dst0 + 4096;

    int rA = warp_m * 64 + (lane & 15);
    int swzA = (rA >> 1) & 3;
    int aoff0 = rA * 64 + ((((lane >> 4)) ^ swzA) << 4);
    int aoff1 = rA * 64 + (((2 + (lane >> 4)) ^ swzA) << 4);
    int rB = warp_n * 32 + (lane & 7) + ((lane >> 4) << 3);
    int swzB = (rB >> 1) & 3;
    int boff0 = rB * 64 + ((((lane >> 3) & 1) ^ swzB) << 4);
    int boff1 = rB * 64 + (((2 + ((lane >> 3) & 1)) ^ swzB) << 4);

    float acc[4][4][4];
    #pragma unroll
    for (int i = 0; i < 4; i++)
        #pragma unroll
        for (int j = 0; j < 4; j++)
            #pragma unroll
            for (int r = 0; r < 4; r++) acc[i][j][r] = 0.f;

    int nt = K >> 5;
    float4 br[4];
    if (BCVT) {
        br[0] = __ldg((const float4*)pB0f);
        br[1] = __ldg((const float4*)(pB0f + 4));
        br[2] = __ldg((const float4*)pB1f);
        br[3] = __ldg((const float4*)(pB1f + 4));
        *(uint4*)(smem + 8192 + dst0) = cvt8(br[0], br[1]);
        *(uint4*)(smem + 8192 + dst1) = cvt8(br[2], br[3]);
        cpa16(sb0 + dst0, pA0);
        cpa16(sb0 + dst1, pA1);
        asm volatile("cp.async.commit_group;");
        if (nt > 1) {
            br[0] = __ldg((const float4*)(pB0f + 32));
            br[1] = __ldg((const float4*)(pB0f + 36));
            br[2] = __ldg((const float4*)(pB1f + 32));
            br[3] = __ldg((const float4*)(pB1f + 36));
            uint32_t s = sb0 + STG_B;
            cpa16(s + dst0, pA0 + 32);
            cpa16(s + dst1, pA1 + 32);
        }
        asm volatile("cp.async.commit_group;");
    } else {
        cpa16(sb0 + 0    + dst0, pA0);
        cpa16(sb0 + 0    + dst1, pA1);
        cpa16(sb0 + 8192 + dst0, pB0h);
        cpa16(sb0 + 8192 + dst1, pB1h);
        asm volatile("cp.async.commit_group;");
        if (nt > 1) {
            uint32_t s = sb0 + STG_B;
            cpa16(s + 0    + dst0, pA0 + 32);
            cpa16(s + 0    + dst1, pA1 + 32);
            cpa16(s + 8192 + dst0, pB0h + 32);
            cpa16(s + 8192 + dst1, pB1h + 32);
        }
        asm volatile("cp.async.commit_group;");
    }
    int buf = 0;
    for (int t = 0; t < nt; t++) {
        asm volatile("cp.async.wait_group 1;");
        __syncthreads();
        if (BCVT) {
            if (t + 1 < nt) {
                int nb1 = buf + 1; if (nb1 >= NSTG) nb1 -= NSTG;
                *(uint4*)(smem + nb1 * STG_B + 8192 + dst0) = cvt8(br[0], br[1]);
                *(uint4*)(smem + nb1 * STG_B + 8192 + dst1) = cvt8(br[2], br[3]);
            }
            if (t + 2 < nt) {
                int kc = (t + 2) << 5;
                br[0] = __ldg((const float4*)(pB0f + kc));
                br[1] = __ldg((const float4*)(pB0f + kc + 4));
                br[2] = __ldg((const float4*)(pB1f + kc));
                br[3] = __ldg((const float4*)(pB1f + kc + 4));
                int nb = buf + 2; if (nb >= NSTG) nb -= NSTG;
                uint32_t s = sb0 + nb * STG_B;
                cpa16(s + dst0, pA0 + kc);
                cpa16(s + dst1, pA1 + kc);
            }
        } else if (t + 2 < nt) {
            int kc = (t + 2) << 5;
            int nb = buf + 2; if (nb >= NSTG) nb -= NSTG;
            uint32_t s = sb0 + nb * STG_B;
            cpa16(s + 0    + dst0, pA0 + kc);
            cpa16(s + 0    + dst1, pA1 + kc);
            cpa16(s + 8192 + dst0, pB0h + kc);
            cpa16(s + 8192 + dst1, pB1h + kc);
        }
        asm volatile("cp.async.commit_group;");

        uint32_t S = sb0 + buf * STG_B;
        #pragma unroll
        for (int sub = 0; sub < 2; sub++) {
            uint32_t aadr = S + (sub ? aoff1 : aoff0);
            uint32_t badr = S + 8192 + (sub ? boff1 : boff0);
            uint32_t ah[4][4];
            #pragma unroll
            for (int im = 0; im < 4; im++) ldsm4(ah[im], aadr + im * 1024);
            uint32_t b0[4], b1[4];
            ldsm4(b0, badr);
            ldsm4(b1, badr + 1024);
            #pragma unroll
            for (int im = 0; im < 4; im++) {
                hmma(acc[im][0], ah[im], b0);
                hmma(acc[im][1], ah[im], b0 + 2);
                hmma(acc[im][2], ah[im], b1);
                hmma(acc[im][3], ah[im], b1 + 2);
            }
        }
        if (++buf == NSTG) buf = 0;
    }

    #pragma unroll
    for (int im = 0; im < 4; im++) {
        #pragma unroll
        for (int half = 0; half < 2; half++) {
            int m = m0 + warp_m * 64 + im * 16 + lr + half * 8;
            if (m >= rows) continue;
            size_t crow = (size_t)(base + m) * (size_t)ldc;
            if (MODE == 0) crow = (size_t)m * ldc;
            #pragma unroll
            for (int in = 0; in < 4; in++) {
                int n = n0 + warp_n * 32 + in * 8 + lc * 2;
                float v0 = acc[im][in][half * 2];
                float v1 = acc[im][in][half * 2 + 1];
                if (EPI == 1) {
                    v0 = 0.5f * v0 * (1.0f + erff(v0 * 0.70710678118654752f));
                    v1 = 0.5f * v1 * (1.0f + erff(v1 * 0.70710678118654752f));
                    __half2 hv = __halves2half2(__float2half_rn(v0), __float2half_rn(v1));
                    *(__half2*)(Ch + crow + n) = hv;
                } else {
                    if (EPI == 2) {
                        v0 += addsrc[(size_t)m * ldadd + n];
                        v1 += addsrc[(size_t)m * ldadd + n + 1];
                    } else if (EPI == 3) {
                        float z0 = v0 + bias[n], z1 = v1 + bias[n + 1];
                        v0 = (z0 > 20.f) ? z0 : log1pf(__expf(z0));
                        v1 = (z1 > 20.f) ? z1 : log1pf(__expf(z1));
                    }
                    *(float2*)(C + crow + n) = make_float2(v0, v1);
                }
            }
        }
    }
}

// ---------------- rmsnorm (writes fp32 + fp16) ----------------
__global__ void rmsnorm_h(const float* __restrict__ x, float* __restrict__ o,
                          __half* __restrict__ oh)
{
    int row = blockIdx.x;
    const float4* xp = (const float4*)(x + (size_t)row * DMODEL);
    float4 v = xp[threadIdx.x];
    float s = v.x * v.x + v.y * v.y + v.z * v.z + v.w * v.w;
    __shared__ float ssum[8];
    #pragma unroll
    for (int off = 16; off; off >>= 1) s += __shfl_xor_sync(0xffffffffu, s, off);
    if ((threadIdx.x & 31) == 0) ssum[threadIdx.x >> 5] = s;
    __syncthreads();
    if (threadIdx.x < 8) {
        float t = ssum[threadIdx.x];
        #pragma unroll
        for (int off = 4; off; off >>= 1) t += __shfl_xor_sync(0xffu, t, off);
        if (threadIdx.x == 0) ssum[0] = t;
    }
    __syncthreads();
    float scale = 32.0f / fmaxf(sqrtf(ssum[0]), 1e-12f);
    float4 w = make_float4(v.x * scale, v.y * scale, v.z * scale, v.w * scale);
    ((float4*)(o + (size_t)row * DMODEL))[threadIdx.x] = w;
    ((uint2*)(oh + (size_t)row * DMODEL))[threadIdx.x] = cvt4(w);
}

// ---------------- split-K SIMT GEMM for skinny x_proj (exact fp32) ----------------
__global__ void __launch_bounds__(256) gemm_sk(
    const float* __restrict__ A, int lda,
    const float* __restrict__ W, int ldw,
    float* __restrict__ Cpart, int ldc,
    int M, int N, int kchunk)
{
    int koff = blockIdx.z * kchunk;
    float* C = Cpart + (size_t)blockIdx.z * M * ldc;
    __shared__ float As[16][68];
    __shared__ float Bs[16][68];
    int tid = threadIdx.x;
    int m0 = blockIdx.x * 64, n0 = blockIdx.y * 64;
    int tx = tid & 15, ty = tid >> 4;
    int lr = tid >> 2;
    int lk = (tid & 3) << 2;
    int am = m0 + lr;
    int wn = n0 + lr;
    bool a_ok = am < M;
    bool w_ok = wn < N;
    const float* Arow = A + (size_t)(a_ok ? am : 0) * lda + koff;
    const float* Wrow = W + (size_t)(w_ok ? wn : 0) * ldw + koff;
    float acc[4][4] = {};
    for (int k0 = 0; k0 < kchunk; k0 += 16) {
        float4 av = a_ok ? *(const float4*)(Arow + k0 + lk) : make_float4(0, 0, 0, 0);
        float4 wv = w_ok ? *(const float4*)(Wrow + k0 + lk) : make_float4(0, 0, 0, 0);
        __syncthreads();
        As[lk][lr] = av.x; As[lk + 1][lr] = av.y; As[lk + 2][lr] = av.z; As[lk + 3][lr] = av.w;
        Bs[lk][lr] = wv.x; Bs[lk + 1][lr] = wv.y; Bs[lk + 2][lr] = wv.z; Bs[lk + 3][lr] = wv.w;
        __syncthreads();
        #pragma unroll
        for (int k = 0; k < 16; k++) {
            float a[4], b[4];
            #pragma unroll
            for (int i = 0; i < 4; i++) a[i] = As[k][ty * 4 + i];
            #pragma unroll
            for (int j = 0; j < 4; j++) b[j] = Bs[k][tx * 4 + j];
            #pragma unroll
            for (int i = 0; i < 4; i++)
                #pragma unroll
                for (int j = 0; j < 4; j++)
                    acc[i][j] += a[i] * b[j];
        }
    }
    #pragma unroll
    for (int i = 0; i < 4; i++) {
        int m = m0 + ty * 4 + i;
        if (m >= M) continue;
        #pragma unroll
        for (int j = 0; j < 4; j++) {
            int n = n0 + tx * 4 + j;
            if (n >= N) continue;
            C[(size_t)m * ldc + n] = acc[i][j];
        }
    }
}

__global__ void reduce_sk(const float* __restrict__ p, float* __restrict__ o,
                          __half* __restrict__ oh, int n)
{
    int i = blockIdx.x * 256 + threadIdx.x;
    if (i >= n) return;
    float s = 0.f;
    #pragma unroll
    for (int j = 0; j < SPLITK; j++) s += p[i + (size_t)j * n];
    o[i] = s;
    oh[i] = __float2half_rn(s);
}

// ---------------- causal depthwise conv(4) + silu: 8 timesteps/thread ----------------
__global__ void conv_silu(const float* __restrict__ xr, const float* __restrict__ cw,
                          const float* __restrict__ cb, float* __restrict__ u)
{
    int idx = blockIdx.x * 256 + threadIdx.x;     // over (LSEQ/8)*DINNER
    int tb = idx >> 11;                           // t-block (0..255)
    int d  = idx & (DINNER - 1);
    int t0 = tb * 8;
    float w0 = cw[d * 4], w1 = cw[d * 4 + 1], w2 = cw[d * 4 + 2], w3 = cw[d * 4 + 3];
    float b = cb[d];
    const float* col = xr + d;
    float v[11];
    #pragma unroll
    for (int i = 0; i < 3; i++) {
        int t = t0 - 3 + i;
        v[i] = (t >= 0) ? col[(size_t)t * (2 * DINNER)] : 0.f;
    }
    #pragma unroll
    for (int i = 3; i < 11; i++)
        v[i] = col[(size_t)(t0 - 3 + i) * (2 * DINNER)];
    float* up = u + d;
    #pragma unroll
    for (int j = 0; j < 8; j++) {
        float s = b + v[j] * w0 + v[j + 1] * w1 + v[j + 2] * w2 + v[j + 3] * w3;
        up[(size_t)(t0 + j) * DINNER] = s / (1.f + __expf(-s));
    }
}

// ---------------- chunked selective scan ----------------
__global__ void scan_part(const float* __restrict__ delta,
                          const float* __restrict__ u,
                          const float* __restrict__ xdbl,
                          const float* __restrict__ A_log,
                          float* __restrict__ Hc, float* __restrict__ Wc)
{
    int lane16 = threadIdx.x & 15;
    int ch = threadIdx.x >> 4;
    int d = blockIdx.x * 8 + ch;
    int c = blockIdx.y;
    float A = -__expf(A_log[d * DSTATE + lane16]);
    float h = 0.f, Wp = 1.f;
    __shared__ float sB[32][16], sdl[32][8], su[32][8];
    for (int t0 = c * CLEN; t0 < (c + 1) * CLEN; t0 += 32) {
        __syncthreads();
        for (int i = threadIdx.x; i < 512; i += 128) {
            int tt = i >> 4, n = i & 15;
            sB[tt][n] = xdbl[(size_t)(t0 + tt) * XDBL + DTRANK + n];
        }
        for (int i = threadIdx.x; i < 256; i += 128) {
            int tt = i >> 3, cc = i & 7;
            size_t off = (size_t)(t0 + tt) * DINNER + blockIdx.x * 8 + cc;
            sdl[tt][cc] = delta[off];
            su[tt][cc]  = u[off];
        }
        __syncthreads();
        for (int tt = 0; tt < 32; tt++) {
            float dl = sdl[tt][ch];
            float dA = __expf(dl * A);
            h = dA * h + dl * sB[tt][lane16] * su[tt][ch];
            Wp *= dA;
        }
    }
    int idx = (c * DINNER + d) * DSTATE + lane16;
    Hc[idx] = h;
    Wc[idx] = Wp;
}

__global__ void scan_fix(const float* __restrict__ Hc, const float* __restrict__ Wc,
                         float* __restrict__ h0)
{
    int idx = blockIdx.x * 256 + threadIdx.x;
    float h = 0.f;
    #pragma unroll
    for (int c = 0; c < NCHUNK; c++) {
        int o = c * DINNER * DSTATE + idx;
        h0[o] = h;
        h = Wc[o] * h + Hc[o];
    }
}

__global__ void scan_final(const float* __restrict__ delta,
                           const float* __restrict__ u,
                           const float* __restrict__ xdbl,
                           const float* __restrict__ A_log,
                           const float* __restrict__ Dvec,
                           const float* __restrict__ xr,
                           const float* __restrict__ h0,
                           __half* __restrict__ yh)
{
    int lane16 = threadIdx.x & 15;
    int ch = threadIdx.x >> 4;
    int d = blockIdx.x * 8 + ch;
    int c = blockIdx.y;
    float A = -__expf(A_log[d * DSTATE + lane16]);
    float Dd = Dvec[d];
    float h = h0[(c * DINNER + d) * DSTATE + lane16];
    __shared__ float sB[32][16], sC[32][16], sdl[32][8], su[32][8], sre[32][8];
    for (int t0 = c * CLEN; t0 < (c + 1) * CLEN; t0 += 32) {
        __syncthreads();
        for (int i = threadIdx.x; i < 512; i += 128) {
            int tt = i >> 4, n = i & 15;
            const float* xb = xdbl + (size_t)(t0 + tt) * XDBL;
            sB[tt][n] = xb[DTRANK + n];
            sC[tt][n] = xb[DTRANK + DSTATE + n];
        }
        for (int i = threadIdx.x; i < 256; i += 128) {
            int tt = i >> 3, cc = i & 7;
            int dd = blockIdx.x * 8 + cc;
            size_t off = (size_t)(t0 + tt) * DINNER + dd;
            sdl[tt][cc] = delta[off];
            su[tt][cc]  = u[off];
            sre[tt][cc] = xr[(size_t)(t0 + tt) * (2 * DINNER) + DINNER + dd];
        }
        __syncthreads();
        for (int tt = 0; tt < 32; tt++) {
            float dl = sdl[tt][ch];
            float uu = su[tt][ch];
            float dA = __expf(dl * A);
            h = dA * h + dl * sB[tt][lane16] * uu;
            float p = h * sC[tt][lane16];
            #pragma unroll
            for (int o = 8; o; o >>= 1) p += __shfl_xor_sync(0xffffffffu, p, o, 16);
            if (lane16 == 0) {
                float yv = p + uu * Dd;
                float r = sre[tt][ch];
                yv *= r / (1.f + __expf(-r));
                yh[(size_t)(t0 + tt) * DINNER + d] = __float2half_rn(yv);
            }
        }
    }
}

// ---------------- gating: GEMV + softmax + top-2 ----------------
__global__ void gate_topk(const float* __restrict__ X, const float* __restrict__ gw,
                          int* __restrict__ te, float* __restrict__ tv)
{
    __shared__ float sg[NEXP * DMODEL];
    for (int i = threadIdx.x; i < NEXP * DMODEL; i += 128) sg[i] = gw[i];
    __syncthreads();
    int warp = threadIdx.x >> 5, lane = threadIdx.x & 31;
    int t = blockIdx.x * 4 + warp;
    const float* xp = X + (size_t)t * DMODEL;
    float acc[NEXP] = {};
    for (int k = lane; k < DMODEL; k += 32) {
        float xv = xp[k];
        #pragma unroll
        for (int e = 0; e < NEXP; e++) acc[e] += xv * sg[e * DMODEL + k];
    }
    #pragma unroll
    for (int e = 0; e < NEXP; e++)
        #pragma unroll
        for (int o = 16; o; o >>= 1) acc[e] += __shfl_xor_sync(0xffffffffu, acc[e], o);
    if (lane == 0) {
        float m = acc[0];
        #pragma unroll
        for (int e = 1; e < NEXP; e++) m = fmaxf(m, acc[e]);
        float g[NEXP];
        #pragma unroll
        for (int e = 0; e < NEXP; e++) g[e] = __expf(acc[e] - m);
        int i0 = 0;
        #pragma unroll
        for (int e = 1; e < NEXP; e++) if (g[e] > g[i0]) i0 = e;
        int i1 = (i0 == 0) ? 1 : 0;
        #pragma unroll
        for (int e = 0; e < NEXP; e++) if (e != i0 && g[e] > g[i1]) i1 = e;
        float inv = 1.f / (g[i0] + g[i1]);
        te[t * 2] = i0; te[t * 2 + 1] = i1;
        tv[t * 2] = g[i0] * inv; tv[t * 2 + 1] = g[i1] * inv;
    }
}

// ---------------- fused routing (1 CTA) ----------------
__global__ void __launch_bounds__(256) route_all(
    const int* __restrict__ te, const float* __restrict__ tv,
    int* __restrict__ off, int* __restrict__ ptok, float* __restrict__ pw,
    int* __restrict__ tok_pair)
{
    __shared__ int scnt[NEXP], soff[NEXP + 1], scur[NEXP];
    int tid = threadIdx.x;
    if (tid < NEXP) scnt[tid] = 0;
    __syncthreads();
    for (int t = tid; t < LSEQ; t += 256) {
        atomicAdd(&scnt[te[t * 2]], 1);
        atomicAdd(&scnt[te[t * 2 + 1]], 1);
    }
    __syncthreads();
    if (tid == 0) {
        int s = 0;
        #pragma unroll
        for (int e = 0; e < NEXP; e++) { soff[e] = s; scur[e] = 0; s += scnt[e]; }
        soff[NEXP] = s;
    }
    __syncthreads();
    if (tid < NEXP + 1) off[tid] = soff[tid];
    for (int t = tid; t < LSEQ; t += 256) {
        #pragma unroll
        for (int k = 0; k < 2; k++) {
            int e = te[t * 2 + k];
            int pos = atomicAdd(&scur[e], 1);
            int p = soff[e] + pos;
            ptok[p] = t;
            pw[p] = tv[t * 2 + k];
            tok_pair[t * 2 + k] = p;
        }
    }
}

// ---------------- final combine ----------------
__global__ void moe_combine(const float* __restrict__ x, const float* __restrict__ y2,
                            const int* __restrict__ tok_pair, const float* __restrict__ pw,
                            float* __restrict__ out)
{
    int i = blockIdx.x * 256 + threadIdx.x;
    int t = i >> 10, n = i & (DMODEL - 1);
    int p0 = tok_pair[t * 2], p1 = tok_pair[t * 2 + 1];
    out[i] = x[i] + pw[p0] * y2[(size_t)p0 * DMODEL + n]
                  + pw[p1] * y2[(size_t)p1 * DMODEL + n];
}

// ---------------- launch ----------------
extern "C" void kernel_launch(void* const* d_in, const int* in_sizes, int n_in,
                              void* d_out, int out_size)
{
    (void)in_sizes; (void)n_in; (void)out_size;
    const float* x          = (const float*)d_in[0];
    const float* in_proj_w  = (const float*)d_in[1];
    const float* conv_w     = (const float*)d_in[2];
    const float* conv_b     = (const float*)d_in[3];
    const float* x_proj_w   = (const float*)d_in[4];
    const float* dt_proj_w  = (const float*)d_in[5];
    const float* dt_proj_b  = (const float*)d_in[6];
    const float* A_log      = (const float*)d_in[7];
    const float* Dvec       = (const float*)d_in[8];
    const float* out_proj_w = (const float*)d_in[9];
    const float* gate_w     = (const float*)d_in[10];
    const float* w1         = (const float*)d_in[11];
    const float* w2         = (const float*)d_in[12];
    float* out = (float*)d_out;

    float *p_xn, *p_xr, *p_u, *p_xdbl, *p_xp, *p_delta, *p_xm2, *p_xm2n, *p_y2, *p_tv, *p_pw;
    float *p_Hc, *p_Wc, *p_h0;
    int *p_te, *p_off, *p_ptok, *p_tp;
    cudaGetSymbolAddress((void**)&p_xn, g_xn);
    cudaGetSymbolAddress((void**)&p_xr, g_xr);
    cudaGetSymbolAddress((void**)&p_u, g_u);
    cudaGetSymbolAddress((void**)&p_xdbl, g_xdbl);
    cudaGetSymbolAddress((void**)&p_xp, g_xp);
    cudaGetSymbolAddress((void**)&p_delta, g_delta);
    cudaGetSymbolAddress((void**)&p_xm2, g_xm2);
    cudaGetSymbolAddress((void**)&p_xm2n, g_xm2n);
    cudaGetSymbolAddress((void**)&p_y2, g_y2);
    cudaGetSymbolAddress((void**)&p_Hc, g_Hc);
    cudaGetSymbolAddress((void**)&p_Wc, g_Wc);
    cudaGetSymbolAddress((void**)&p_h0, g_h0);
    cudaGetSymbolAddress((void**)&p_te, g_top_e);
    cudaGetSymbolAddress((void**)&p_tv, g_top_v);
    cudaGetSymbolAddress((void**)&p_off, g_off);
    cudaGetSymbolAddress((void**)&p_ptok, g_ptok);
    cudaGetSymbolAddress((void**)&p_pw, g_pw);
    cudaGetSymbolAddress((void**)&p_tp, g_tok_pair);

    __half *xnh, *xdh, *yh, *x2h, *hh, *wih, *wdh, *woh;
    cudaGetSymbolAddress((void**)&xnh, h_xn);
    cudaGetSymbolAddress((void**)&xdh, h_xd);
    cudaGetSymbolAddress((void**)&yh,  h_y);
    cudaGetSymbolAddress((void**)&x2h, h_x2);
    cudaGetSymbolAddress((void**)&hh,  h_h);
    cudaGetSymbolAddress((void**)&wih, h_wi);
    cudaGetSymbolAddress((void**)&wdh, h_wd);
    cudaGetSymbolAddress((void**)&woh, h_wo);

    const int SMEM = NSTG * STG_B;   // 48 KB
    cudaFuncSetAttribute((const void*)hgemm<0, 0, 0>, cudaFuncAttributeMaxDynamicSharedMemorySize, SMEM);
    cudaFuncSetAttribute((const void*)hgemm<3, 0, 0>, cudaFuncAttributeMaxDynamicSharedMemorySize, SMEM);
    cudaFuncSetAttribute((const void*)hgemm<2, 0, 0>, cudaFuncAttributeMaxDynamicSharedMemorySize, SMEM);
    cudaFuncSetAttribute((const void*)hgemm<1, 1, 1>, cudaFuncAttributeMaxDynamicSharedMemorySize, SMEM);
    cudaFuncSetAttribute((const void*)hgemm<0, 2, 1>, cudaFuncAttributeMaxDynamicSharedMemorySize, SMEM);

    // 0. convert small weights to fp16 (w1/w2 converted in-GEMM)
    conv_h<<<(2 * DINNER * DMODEL / 4 + 255) / 256, 256>>>((const float4*)in_proj_w, (uint2*)wih, 2 * DINNER * DMODEL / 4);
    conv_h<<<(DINNER * DTRANK / 4 + 255) / 256, 256>>>((const float4*)dt_proj_w, (uint2*)wdh, DINNER * DTRANK / 4);
    conv_h<<<(DMODEL * DINNER / 4 + 255) / 256, 256>>>((const float4*)out_proj_w, (uint2*)woh, DMODEL * DINNER / 4);

    // 1. xn = rmsnorm(x)
    rmsnorm_h<<<LSEQ, 256>>>(x, p_xn, xnh);
    // 2. xr = xn @ in_proj^T
    hgemm<0, 0, 0><<<dim3(16, 32), 256, SMEM>>>(xnh, DMODEL, wih, nullptr, DMODEL,
                                                p_xr, 2 * DINNER, LSEQ, 2 * DINNER,
                                                nullptr, nullptr, 0, nullptr, nullptr, nullptr);
    // 3. conv + silu (8 timesteps per thread)
    conv_silu<<<(LSEQ / 8) * DINNER / 256, 256>>>(p_xr, conv_w, conv_b, p_u);
    // 4. x_dbl = u @ x_proj^T (split-K exact fp32)
    gemm_sk<<<dim3(32, 2, SPLITK), 256>>>(p_u, DINNER, x_proj_w, DINNER,
                                          p_xp, XDBL, LSEQ, XDBL, DINNER / SPLITK);
    reduce_sk<<<(LSEQ * XDBL + 255) / 256, 256>>>(p_xp, p_xdbl, xdh, LSEQ * XDBL);
    // 5. delta = softplus(dt @ dt_proj^T + b)
    hgemm<3, 0, 0><<<dim3(16, 16), 256, SMEM>>>(xdh, XDBL, wdh, nullptr, DTRANK,
                                                p_delta, DINNER, LSEQ, DINNER,
                                                dt_proj_b, nullptr, 0, nullptr, nullptr, nullptr);
    // 6. chunked selective scan -> y fp16
    scan_part<<<dim3(DINNER / 8, NCHUNK), 128>>>(p_delta, p_u, p_xdbl, A_log, p_Hc, p_Wc);
    scan_fix<<<DINNER * DSTATE / 256, 256>>>(p_Hc, p_Wc, p_h0);
    scan_final<<<dim3(DINNER / 8, NCHUNK), 128>>>(p_delta, p_u, p_xdbl, A_log, Dvec,
                                                  p_xr, p_h0, yh);
    // 7. xm2 = y @ out_proj^T + xn
    hgemm<2, 0, 0><<<dim3(16, 8), 256, SMEM>>>(yh, DINNER, woh, nullptr, DINNER,
                                               p_xm2, DMODEL, LSEQ, DMODEL,
                                               nullptr, p_xn, DMODEL, nullptr, nullptr, nullptr);
    // 8. xm2n = rmsnorm(xm2)
    rmsnorm_h<<<LSEQ, 256>>>(p_xm2, p_xm2n, x2h);
    // 9. gating + routing (fused)
    gate_topk<<<LSEQ / 4, 128>>>(p_xm2n, gate_w, p_te, p_tv);
    route_all<<<1, 256>>>(p_te, p_tv, p_off, p_ptok, p_pw, p_tp);
    // 10. expert GEMMs (fp32 weights, converted in-kernel)
    hgemm<1, 1, 1><<<dim3(32, 32, NEXP), 256, SMEM>>>(x2h, DMODEL, nullptr, w1, DMODEL,
                                                      nullptr, HIDDEN, 0, HIDDEN,
                                                      nullptr, nullptr, 0, p_off, p_ptok, hh);
    hgemm<0, 2, 1><<<dim3(32, 8, NEXP), 256, SMEM>>>(hh, HIDDEN, nullptr, w2, HIDDEN,
                                                     p_y2, DMODEL, 0, DMODEL,
                                                     nullptr, nullptr, 0, p_off, nullptr, nullptr);
    moe_combine<<<(LSEQ * DMODEL) / 256, 256>>>(x, p_y2, p_tp, p_pw, out);
}

// round 17
// speedup vs baseline: 1.6529x; 1.0134x over previous
#include <cuda_runtime.h>
#include <cuda_fp16.h>
#include <math.h>
#include <stdint.h>

// ---------------- problem constants ----------------
#define LSEQ   2048
#define DMODEL 1024
#define DINNER 2048
#define DSTATE 16
#define DTRANK 64
#define XDBL   96
#define NEXP   8
#define HIDDEN 4096
#define NPAIR  4096
#define SPLITK 16
#define NCHUNK 16
#define CLEN   128   // LSEQ / NCHUNK

// ---------------- fp32 scratch ----------------
__device__ float g_xn   [LSEQ * DMODEL];
__device__ float g_xr   [LSEQ * 2 * DINNER];
__device__ float g_u    [LSEQ * DINNER];
__device__ float g_xdbl [LSEQ * XDBL];
__device__ float g_xp   [SPLITK * LSEQ * XDBL];
__device__ float g_delta[LSEQ * DINNER];
__device__ float g_xm2  [LSEQ * DMODEL];
__device__ float g_xm2n [LSEQ * DMODEL];
__device__ float g_y2   [(size_t)NPAIR * DMODEL];
__device__ float g_Hc   [NCHUNK * DINNER * DSTATE];
__device__ float g_Wc   [NCHUNK * DINNER * DSTATE];
__device__ int   g_top_e[LSEQ * 2];
__device__ float g_top_v[LSEQ * 2];
__device__ int   g_off[NEXP + 1];
__device__ int   g_ptok[NPAIR];
__device__ float g_pw  [NPAIR];
__device__ int   g_tok_pair[LSEQ * 2];

// ---------------- fp16 scratch ----------------
__device__ __align__(16) __half h_xn [LSEQ * DMODEL];
__device__ __align__(16) __half h_xd [LSEQ * XDBL];
__device__ __align__(16) __half h_y  [LSEQ * DINNER];
__device__ __align__(16) __half h_x2 [LSEQ * DMODEL];
__device__ __align__(16) __half h_h  [(size_t)NPAIR * HIDDEN];
__device__ __align__(16) __half h_wi [2 * DINNER * DMODEL];
__device__ __align__(16) __half h_wd [DINNER * DTRANK];
__device__ __align__(16) __half h_wo [DMODEL * DINNER];

// ---------------- helpers ----------------
__device__ __forceinline__ void cpa16(uint32_t dst, const void* src)
{
    asm volatile("cp.async.cg.shared.global [%0], [%1], 16;" :: "r"(dst), "l"(src));
}

__device__ __forceinline__ void ldsm4(uint32_t* r, uint32_t a)
{
    asm volatile("ldmatrix.sync.aligned.m8n8.x4.shared.b16 {%0,%1,%2,%3}, [%4];"
                 : "=r"(r[0]), "=r"(r[1]), "=r"(r[2]), "=r"(r[3]) : "r"(a));
}

__device__ __forceinline__ void hmma(float* d, const uint32_t* a, const uint32_t* b)
{
    asm volatile(
        "mma.sync.aligned.m16n8k16.row.col.f32.f16.f16.f32 "
        "{%0,%1,%2,%3},{%4,%5,%6,%7},{%8,%9},{%0,%1,%2,%3};\n"
        : "+f"(d[0]), "+f"(d[1]), "+f"(d[2]), "+f"(d[3])
        : "r"(a[0]), "r"(a[1]), "r"(a[2]), "r"(a[3]), "r"(b[0]), "r"(b[1]));
}

__device__ __forceinline__ uint2 cvt4(float4 v)
{
    __half2 h01 = __halves2half2(__float2half_rn(v.x), __float2half_rn(v.y));
    __half2 h23 = __halves2half2(__float2half_rn(v.z), __float2half_rn(v.w));
    return make_uint2(*(uint32_t*)&h01, *(uint32_t*)&h23);
}

__device__ __forceinline__ uint4 cvt8(float4 a, float4 b)
{
    uint2 lo = cvt4(a), hi = cvt4(b);
    return make_uint4(lo.x, lo.y, hi.x, hi.y);
}

// ---------------- fused weight convert: 3 segments, grid-stride ----------------
__global__ void conv_h3(const float4* __restrict__ c1, uint2* __restrict__ d1, int n1,
                        const float4* __restrict__ c2, uint2* __restrict__ d2, int n2,
                        const float4* __restrict__ c3, uint2* __restrict__ d3, int n3)
{
    size_t total = (size_t)n1 + n2 + n3;
    size_t stride = (size_t)gridDim.x * 256;
    for (size_t i = (size_t)blockIdx.x * 256 + threadIdx.x; i < total; i += stride) {
        size_t j = i;
        const float4* s; uint2* d;
        if (j < (size_t)n1) { s = c1; d = d1; }
        else if ((j -= n1) < (size_t)n2) { s = c2; d = d2; }
        else { j -= n2; s = c3; d = d3; }
        d[j] = cvt4(s[j]);
    }
}

// ---------------- fp16 tensor GEMM: C = epi(A @ W^T) ----------------
#define NSTG 3
#define STG_B 16384
template<int EPI, int MODE, int BCVT>
__global__ void __launch_bounds__(256, 2) hgemm(
    const __half* __restrict__ Aq, int lda,
    const __half* __restrict__ Wq, const float* __restrict__ Wf, int K,
    float* __restrict__ C, int ldc, int M, int N,
    const float* __restrict__ bias, const float* __restrict__ addsrc, int ldadd,
    const int* __restrict__ off, const int* __restrict__ ptok,
    __half* __restrict__ Ch)
{
    extern __shared__ __align__(16) uint8_t smem[];
    int base = 0, rows = M;
    const __half* W = Wq;
    const float* WF = Wf;
    if (MODE != 0) {
        int e = blockIdx.z;
        base = off[e];
        rows = off[e + 1] - base;
        if (BCVT) WF += (size_t)e * (size_t)N * K;
        else      W  += (size_t)e * (size_t)N * K;
    }
    int m0 = blockIdx.x * 128;
    if (m0 >= rows) return;
    int n0 = blockIdx.y * 128;

    int tid = threadIdx.x;
    int wid = tid >> 5, lane = tid & 31;
    int lr = lane >> 2, lc = lane & 3;
    int warp_m = wid >> 2, warp_n = wid & 3;

    int qg = tid & 3;
    int ar = tid >> 2;
    int rA0 = m0 + ar, rA1 = rA0 + 64;
    int c0 = rA0 < rows ? rA0 : rows - 1;
    int c1 = rA1 < rows ? rA1 : rows - 1;
    int gA0, gA1;
    if (MODE == 1)      { gA0 = ptok[base + c0]; gA1 = ptok[base + c1]; }
    else if (MODE == 2) { gA0 = base + c0;       gA1 = base + c1; }
    else                { gA0 = c0;              gA1 = c1; }

    const __half* pA0 = Aq + (size_t)gA0 * lda + qg * 8;
    const __half* pA1 = Aq + (size_t)gA1 * lda + qg * 8;
    const __half* pB0h = BCVT ? nullptr : (W + (size_t)(n0 + ar) * K + qg * 8);
    const __half* pB1h = BCVT ? nullptr : (W + (size_t)(n0 + ar + 64) * K + qg * 8);
    const float*  pB0f = BCVT ? (WF + (size_t)(n0 + ar) * K + qg * 8) : nullptr;
    const float*  pB1f = BCVT ? (WF + (size_t)(n0 + ar + 64) * K + qg * 8) : nullptr;

    uint32_t sb0 = (uint32_t)__cvta_generic_to_shared(smem);
    int dst0 = ar * 64 + ((qg ^ ((ar >> 1) & 3)) << 4);
    int dst1 = dst0 + 4096;

    int rA = warp_m * 64 + (lane & 15);
    int swzA = (rA >> 1) & 3;
    int aoff0 = rA * 64 + ((((lane >> 4)) ^ swzA) << 4);
    int aoff1 = rA * 64 + (((2 + (lane >> 4)) ^ swzA) << 4);
    int rB = warp_n * 32 + (lane & 7) + ((lane >> 4) << 3);
    int swzB = (rB >> 1) & 3;
    int boff0 = rB * 64 + ((((lane >> 3) & 1) ^ swzB) << 4);
    int boff1 = rB * 64 + (((2 + ((lane >> 3) & 1)) ^ swzB) << 4);

    float acc[4][4][4];
    #pragma unroll
    for (int i = 0; i < 4; i++)
        #pragma unroll
        for (int j = 0; j < 4; j++)
            #pragma unroll
            for (int r = 0; r < 4; r++) acc[i][j][r] = 0.f;

    int nt = K >> 5;
    float4 br[4];
    if (BCVT) {
        br[0] = __ldg((const float4*)pB0f);
        br[1] = __ldg((const float4*)(pB0f + 4));
        br[2] = __ldg((const float4*)pB1f);
        br[3] = __ldg((const float4*)(pB1f + 4));
        *(uint4*)(smem + 8192 + dst0) = cvt8(br[0], br[1]);
        *(uint4*)(smem + 8192 + dst1) = cvt8(br[2], br[3]);
        cpa16(sb0 + dst0, pA0);
        cpa16(sb0 + dst1, pA1);
        asm volatile("cp.async.commit_group;");
        if (nt > 1) {
            br[0] = __ldg((const float4*)(pB0f + 32));
            br[1] = __ldg((const float4*)(pB0f + 36));
            br[2] = __ldg((const float4*)(pB1f + 32));
            br[3] = __ldg((const float4*)(pB1f + 36));
            uint32_t s = sb0 + STG_B;
            cpa16(s + dst0, pA0 + 32);
            cpa16(s + dst1, pA1 + 32);
        }
        asm volatile("cp.async.commit_group;");
    } else {
        cpa16(sb0 + 0    + dst0, pA0);
        cpa16(sb0 + 0    + dst1, pA1);
        cpa16(sb0 + 8192 + dst0, pB0h);
        cpa16(sb0 + 8192 + dst1, pB1h);
        asm volatile("cp.async.commit_group;");
        if (nt > 1) {
            uint32_t s = sb0 + STG_B;
            cpa16(s + 0    + dst0, pA0 + 32);
            cpa16(s + 0    + dst1, pA1 + 32);
            cpa16(s + 8192 + dst0, pB0h + 32);
            cpa16(s + 8192 + dst1, pB1h + 32);
        }
        asm volatile("cp.async.commit_group;");
    }
    int buf = 0;
    for (int t = 0; t < nt; t++) {
        asm volatile("cp.async.wait_group 1;");
        __syncthreads();
        if (BCVT) {
            if (t + 1 < nt) {
                int nb1 = buf + 1; if (nb1 >= NSTG) nb1 -= NSTG;
                *(uint4*)(smem + nb1 * STG_B + 8192 + dst0) = cvt8(br[0], br[1]);
                *(uint4*)(smem + nb1 * STG_B + 8192 + dst1) = cvt8(br[2], br[3]);
            }
            if (t + 2 < nt) {
                int kc = (t + 2) << 5;
                br[0] = __ldg((const float4*)(pB0f + kc));
                br[1] = __ldg((const float4*)(pB0f + kc + 4));
                br[2] = __ldg((const float4*)(pB1f + kc));
                br[3] = __ldg((const float4*)(pB1f + kc + 4));
                int nb = buf + 2; if (nb >= NSTG) nb -= NSTG;
                uint32_t s = sb0 + nb * STG_B;
                cpa16(s + dst0, pA0 + kc);
                cpa16(s + dst1, pA1 + kc);
            }
        } else if (t + 2 < nt) {
            int kc = (t + 2) << 5;
            int nb = buf + 2; if (nb >= NSTG) nb -= NSTG;
            uint32_t s = sb0 + nb * STG_B;
            cpa16(s + 0    + dst0, pA0 + kc);
            cpa16(s + 0    + dst1, pA1 + kc);
            cpa16(s + 8192 + dst0, pB0h + kc);
            cpa16(s + 8192 + dst1, pB1h + kc);
        }
        asm volatile("cp.async.commit_group;");

        uint32_t S = sb0 + buf * STG_B;
        #pragma unroll
        for (int sub = 0; sub < 2; sub++) {
            uint32_t aadr = S + (sub ? aoff1 : aoff0);
            uint32_t badr = S + 8192 + (sub ? boff1 : boff0);
            uint32_t ah[4][4];
            #pragma unroll
            for (int im = 0; im < 4; im++) ldsm4(ah[im], aadr + im * 1024);
            uint32_t b0[4], b1[4];
            ldsm4(b0, badr);
            ldsm4(b1, badr + 1024);
            #pragma unroll
            for (int im = 0; im < 4; im++) {
                hmma(acc[im][0], ah[im], b0);
                hmma(acc[im][1], ah[im], b0 + 2);
                hmma(acc[im][2], ah[im], b1);
                hmma(acc[im][3], ah[im], b1 + 2);
            }
        }
        if (++buf == NSTG) buf = 0;
    }

    #pragma unroll
    for (int im = 0; im < 4; im++) {
        #pragma unroll
        for (int half = 0; half < 2; half++) {
            int m = m0 + warp_m * 64 + im * 16 + lr + half * 8;
            if (m >= rows) continue;
            size_t crow = (size_t)(base + m) * (size_t)ldc;
            if (MODE == 0) crow = (size_t)m * ldc;
            #pragma unroll
            for (int in = 0; in < 4; in++) {
                int n = n0 + warp_n * 32 + in * 8 + lc * 2;
                float v0 = acc[im][in][half * 2];
                float v1 = acc[im][in][half * 2 + 1];
                if (EPI == 1) {
                    v0 = 0.5f * v0 * (1.0f + erff(v0 * 0.70710678118654752f));
                    v1 = 0.5f * v1 * (1.0f + erff(v1 * 0.70710678118654752f));
                    __half2 hv = __halves2half2(__float2half_rn(v0), __float2half_rn(v1));
                    *(__half2*)(Ch + crow + n) = hv;
                } else {
                    if (EPI == 2) {
                        v0 += addsrc[(size_t)m * ldadd + n];
                        v1 += addsrc[(size_t)m * ldadd + n + 1];
                    } else if (EPI == 3) {
                        float z0 = v0 + bias[n], z1 = v1 + bias[n + 1];
                        v0 = (z0 > 20.f) ? z0 : log1pf(__expf(z0));
                        v1 = (z1 > 20.f) ? z1 : log1pf(__expf(z1));
                    }
                    *(float2*)(C + crow + n) = make_float2(v0, v1);
                }
            }
        }
    }
}

// ---------------- rmsnorm (writes fp32 + fp16) ----------------
__global__ void rmsnorm_h(const float* __restrict__ x, float* __restrict__ o,
                          __half* __restrict__ oh)
{
    int row = blockIdx.x;
    const float4* xp = (const float4*)(x + (size_t)row * DMODEL);
    float4 v = xp[threadIdx.x];
    float s = v.x * v.x + v.y * v.y + v.z * v.z + v.w * v.w;
    __shared__ float ssum[8];
    #pragma unroll
    for (int off = 16; off; off >>= 1) s += __shfl_xor_sync(0xffffffffu, s, off);
    if ((threadIdx.x & 31) == 0) ssum[threadIdx.x >> 5] = s;
    __syncthreads();
    if (threadIdx.x < 8) {
        float t = ssum[threadIdx.x];
        #pragma unroll
        for (int off = 4; off; off >>= 1) t += __shfl_xor_sync(0xffu, t, off);
        if (threadIdx.x == 0) ssum[0] = t;
    }
    __syncthreads();
    float scale = 32.0f / fmaxf(sqrtf(ssum[0]), 1e-12f);
    float4 w = make_float4(v.x * scale, v.y * scale, v.z * scale, v.w * scale);
    ((float4*)(o + (size_t)row * DMODEL))[threadIdx.x] = w;
    ((uint2*)(oh + (size_t)row * DMODEL))[threadIdx.x] = cvt4(w);
}

// ---------------- split-K SIMT GEMM for skinny x_proj (exact fp32) ----------------
__global__ void __launch_bounds__(256) gemm_sk(
    const float* __restrict__ A, int lda,
    const float* __restrict__ W, int ldw,
    float* __restrict__ Cpart, int ldc,
    int M, int N, int kchunk)
{
    int koff = blockIdx.z * kchunk;
    float* C = Cpart + (size_t)blockIdx.z * M * ldc;
    __shared__ float As[16][68];
    __shared__ float Bs[16][68];
    int tid = threadIdx.x;
    int m0 = blockIdx.x * 64, n0 = blockIdx.y * 64;
    int tx = tid & 15, ty = tid >> 4;
    int lr = tid >> 2;
    int lk = (tid & 3) << 2;
    int am = m0 + lr;
    int wn = n0 + lr;
    bool a_ok = am < M;
    bool w_ok = wn < N;
    const float* Arow = A + (size_t)(a_ok ? am : 0) * lda + koff;
    const float* Wrow = W + (size_t)(w_ok ? wn : 0) * ldw + koff;
    float acc[4][4] = {};
    for (int k0 = 0; k0 < kchunk; k0 += 16) {
        float4 av = a_ok ? *(const float4*)(Arow + k0 + lk) : make_float4(0, 0, 0, 0);
        float4 wv = w_ok ? *(const float4*)(Wrow + k0 + lk) : make_float4(0, 0, 0, 0);
        __syncthreads();
        As[lk][lr] = av.x; As[lk + 1][lr] = av.y; As[lk + 2][lr] = av.z; As[lk + 3][lr] = av.w;
        Bs[lk][lr] = wv.x; Bs[lk + 1][lr] = wv.y; Bs[lk + 2][lr] = wv.z; Bs[lk + 3][lr] = wv.w;
        __syncthreads();
        #pragma unroll
        for (int k = 0; k < 16; k++) {
            float a[4], b[4];
            #pragma unroll
            for (int i = 0; i < 4; i++) a[i] = As[k][ty * 4 + i];
            #pragma unroll
            for (int j = 0; j < 4; j++) b[j] = Bs[k][tx * 4 + j];
            #pragma unroll
            for (int i = 0; i < 4; i++)
                #pragma unroll
                for (int j = 0; j < 4; j++)
                    acc[i][j] += a[i] * b[j];
        }
    }
    #pragma unroll
    for (int i = 0; i < 4; i++) {
        int m = m0 + ty * 4 + i;
        if (m >= M) continue;
        #pragma unroll
        for (int j = 0; j < 4; j++) {
            int n = n0 + tx * 4 + j;
            if (n >= N) continue;
            C[(size_t)m * ldc + n] = acc[i][j];
        }
    }
}

__global__ void reduce_sk(const float* __restrict__ p, float* __restrict__ o,
                          __half* __restrict__ oh, int n)
{
    int i = blockIdx.x * 256 + threadIdx.x;
    if (i >= n) return;
    float s = 0.f;
    #pragma unroll
    for (int j = 0; j < SPLITK; j++) s += p[i + (size_t)j * n];
    o[i] = s;
    oh[i] = __float2half_rn(s);
}

// ---------------- causal depthwise conv(4) + silu: 8 timesteps/thread ----------------
__global__ void conv_silu(const float* __restrict__ xr, const float* __restrict__ cw,
                          const float* __restrict__ cb, float* __restrict__ u)
{
    int idx = blockIdx.x * 256 + threadIdx.x;
    int tb = idx >> 11;
    int d  = idx & (DINNER - 1);
    int t0 = tb * 8;
    float w0 = cw[d * 4], w1 = cw[d * 4 + 1], w2 = cw[d * 4 + 2], w3 = cw[d * 4 + 3];
    float b = cb[d];
    const float* col = xr + d;
    float v[11];
    #pragma unroll
    for (int i = 0; i < 3; i++) {
        int t = t0 - 3 + i;
        v[i] = (t >= 0) ? col[(size_t)t * (2 * DINNER)] : 0.f;
    }
    #pragma unroll
    for (int i = 3; i < 11; i++)
        v[i] = col[(size_t)(t0 - 3 + i) * (2 * DINNER)];
    float* up = u + d;
    #pragma unroll
    for (int j = 0; j < 8; j++) {
        float s = b + v[j] * w0 + v[j + 1] * w1 + v[j + 2] * w2 + v[j + 3] * w3;
        up[(size_t)(t0 + j) * DINNER] = s / (1.f + __expf(-s));
    }
}

// ---------------- chunked selective scan ----------------
__global__ void scan_part(const float* __restrict__ delta,
                          const float* __restrict__ u,
                          const float* __restrict__ xdbl,
                          const float* __restrict__ A_log,
                          float* __restrict__ Hc, float* __restrict__ Wc)
{
    int lane16 = threadIdx.x & 15;
    int ch = threadIdx.x >> 4;
    int d = blockIdx.x * 8 + ch;
    int c = blockIdx.y;
    float A = -__expf(A_log[d * DSTATE + lane16]);
    float h = 0.f, Wp = 1.f;
    __shared__ float sB[32][16], sdl[32][8], su[32][8];
    for (int t0 = c * CLEN; t0 < (c + 1) * CLEN; t0 += 32) {
        __syncthreads();
        for (int i = threadIdx.x; i < 512; i += 128) {
            int tt = i >> 4, n = i & 15;
            sB[tt][n] = xdbl[(size_t)(t0 + tt) * XDBL + DTRANK + n];
        }
        for (int i = threadIdx.x; i < 256; i += 128) {
            int tt = i >> 3, cc = i & 7;
            size_t off = (size_t)(t0 + tt) * DINNER + blockIdx.x * 8 + cc;
            sdl[tt][cc] = delta[off];
            su[tt][cc]  = u[off];
        }
        __syncthreads();
        for (int tt = 0; tt < 32; tt++) {
            float dl = sdl[tt][ch];
            float dA = __expf(dl * A);
            h = dA * h + dl * sB[tt][lane16] * su[tt][ch];
            Wp *= dA;
        }
    }
    int idx = (c * DINNER + d) * DSTATE + lane16;
    Hc[idx] = h;
    Wc[idx] = Wp;
}

// phase B+C fused: fold preceding chunk summaries, then rerun chunk and emit y
__global__ void scan_final(const float* __restrict__ delta,
                           const float* __restrict__ u,
                           const float* __restrict__ xdbl,
                           const float* __restrict__ A_log,
                           const float* __restrict__ Dvec,
                           const float* __restrict__ xr,
                           const float* __restrict__ Hc,
                           const float* __restrict__ Wc,
                           __half* __restrict__ yh)
{
    int lane16 = threadIdx.x & 15;
    int ch = threadIdx.x >> 4;
    int d = blockIdx.x * 8 + ch;
    int c = blockIdx.y;
    float A = -__expf(A_log[d * DSTATE + lane16]);
    float Dd = Dvec[d];
    // entry state: fold chunks 0..c-1 (same recurrence as the old scan_fix)
    float h = 0.f;
    int so = d * DSTATE + lane16;
    for (int j = 0; j < c; j++) {
        int o = j * DINNER * DSTATE + so;
        h = Wc[o] * h + Hc[o];
    }
    __shared__ float sB[32][16], sC[32][16], sdl[32][8], su[32][8], sre[32][8];
    for (int t0 = c * CLEN; t0 < (c + 1) * CLEN; t0 += 32) {
        __syncthreads();
        for (int i = threadIdx.x; i < 512; i += 128) {
            int tt = i >> 4, n = i & 15;
            const float* xb = xdbl + (size_t)(t0 + tt) * XDBL;
            sB[tt][n] = xb[DTRANK + n];
            sC[tt][n] = xb[DTRANK + DSTATE + n];
        }
        for (int i = threadIdx.x; i < 256; i += 128) {
            int tt = i >> 3, cc = i & 7;
            int dd = blockIdx.x * 8 + cc;
            size_t off = (size_t)(t0 + tt) * DINNER + dd;
            sdl[tt][cc] = delta[off];
            su[tt][cc]  = u[off];
            sre[tt][cc] = xr[(size_t)(t0 + tt) * (2 * DINNER) + DINNER + dd];
        }
        __syncthreads();
        for (int tt = 0; tt < 32; tt++) {
            float dl = sdl[tt][ch];
            float uu = su[tt][ch];
            float dA = __expf(dl * A);
            h = dA * h + dl * sB[tt][lane16] * uu;
            float p = h * sC[tt][lane16];
            #pragma unroll
            for (int o = 8; o; o >>= 1) p += __shfl_xor_sync(0xffffffffu, p, o, 16);
            if (lane16 == 0) {
                float yv = p + uu * Dd;
                float r = sre[tt][ch];
                yv *= r / (1.f + __expf(-r));
                yh[(size_t)(t0 + tt) * DINNER + d] = __float2half_rn(yv);
            }
        }
    }
}

// ---------------- gating: GEMV + softmax + top-2 ----------------
__global__ void gate_topk(const float* __restrict__ X, const float* __restrict__ gw,
                          int* __restrict__ te, float* __restrict__ tv)
{
    __shared__ float sg[NEXP * DMODEL];
    for (int i = threadIdx.x; i < NEXP * DMODEL; i += 128) sg[i] = gw[i];
    __syncthreads();
    int warp = threadIdx.x >> 5, lane = threadIdx.x & 31;
    int t = blockIdx.x * 4 + warp;
    const float* xp = X + (size_t)t * DMODEL;
    float acc[NEXP] = {};
    for (int k = lane; k < DMODEL; k += 32) {
        float xv = xp[k];
        #pragma unroll
        for (int e = 0; e < NEXP; e++) acc[e] += xv * sg[e * DMODEL + k];
    }
    #pragma unroll
    for (int e = 0; e < NEXP; e++)
        #pragma unroll
        for (int o = 16; o; o >>= 1) acc[e] += __shfl_xor_sync(0xffffffffu, acc[e], o);
    if (lane == 0) {
        float m = acc[0];
        #pragma unroll
        for (int e = 1; e < NEXP; e++) m = fmaxf(m, acc[e]);
        float g[NEXP];
        #pragma unroll
        for (int e = 0; e < NEXP; e++) g[e] = __expf(acc[e] - m);
        int i0 = 0;
        #pragma unroll
        for (int e = 1; e < NEXP; e++) if (g[e] > g[i0]) i0 = e;
        int i1 = (i0 == 0) ? 1 : 0;
        #pragma unroll
        for (int e = 0; e < NEXP; e++) if (e != i0 && g[e] > g[i1]) i1 = e;
        float inv = 1.f / (g[i0] + g[i1]);
        te[t * 2] = i0; te[t * 2 + 1] = i1;
        tv[t * 2] = g[i0] * inv; tv[t * 2 + 1] = g[i1] * inv;
    }
}

// ---------------- fused routing (1 CTA) ----------------
__global__ void __launch_bounds__(256) route_all(
    const int* __restrict__ te, const float* __restrict__ tv,
    int* __restrict__ off, int* __restrict__ ptok, float* __restrict__ pw,
    int* __restrict__ tok_pair)
{
    __shared__ int scnt[NEXP], soff[NEXP + 1], scur[NEXP];
    int tid = threadIdx.x;
    if (tid < NEXP) scnt[tid] = 0;
    __syncthreads();
    for (int t = tid; t < LSEQ; t += 256) {
        atomicAdd(&scnt[te[t * 2]], 1);
        atomicAdd(&scnt[te[t * 2 + 1]], 1);
    }
    __syncthreads();
    if (tid == 0) {
        int s = 0;
        #pragma unroll
        for (int e = 0; e < NEXP; e++) { soff[e] = s; scur[e] = 0; s += scnt[e]; }
        soff[NEXP] = s;
    }
    __syncthreads();
    if (tid < NEXP + 1) off[tid] = soff[tid];
    for (int t = tid; t < LSEQ; t += 256) {
        #pragma unroll
        for (int k = 0; k < 2; k++) {
            int e = te[t * 2 + k];
            int pos = atomicAdd(&scur[e], 1);
            int p = soff[e] + pos;
            ptok[p] = t;
            pw[p] = tv[t * 2 + k];
            tok_pair[t * 2 + k] = p;
        }
    }
}

// ---------------- final combine ----------------
__global__ void moe_combine(const float* __restrict__ x, const float* __restrict__ y2,
                            const int* __restrict__ tok_pair, const float* __restrict__ pw,
                            float* __restrict__ out)
{
    int i = blockIdx.x * 256 + threadIdx.x;
    int t = i >> 10, n = i & (DMODEL - 1);
    int p0 = tok_pair[t * 2], p1 = tok_pair[t * 2 + 1];
    out[i] = x[i] + pw[p0] * y2[(size_t)p0 * DMODEL + n]
                  + pw[p1] * y2[(size_t)p1 * DMODEL + n];
}

// ---------------- launch ----------------
extern "C" void kernel_launch(void* const* d_in, const int* in_sizes, int n_in,
                              void* d_out, int out_size)
{
    (void)in_sizes; (void)n_in; (void)out_size;
    const float* x          = (const float*)d_in[0];
    const float* in_proj_w  = (const float*)d_in[1];
    const float* conv_w     = (const float*)d_in[2];
    const float* conv_b     = (const float*)d_in[3];
    const float* x_proj_w   = (const float*)d_in[4];
    const float* dt_proj_w  = (const float*)d_in[5];
    const float* dt_proj_b  = (const float*)d_in[6];
    const float* A_log      = (const float*)d_in[7];
    const float* Dvec       = (const float*)d_in[8];
    const float* out_proj_w = (const float*)d_in[9];
    const float* gate_w     = (const float*)d_in[10];
    const float* w1         = (const float*)d_in[11];
    const float* w2         = (const float*)d_in[12];
    float* out = (float*)d_out;

    float *p_xn, *p_xr, *p_u, *p_xdbl, *p_xp, *p_delta, *p_xm2, *p_xm2n, *p_y2, *p_tv, *p_pw;
    float *p_Hc, *p_Wc;
    int *p_te, *p_off, *p_ptok, *p_tp;
    cudaGetSymbolAddress((void**)&p_xn, g_xn);
    cudaGetSymbolAddress((void**)&p_xr, g_xr);
    cudaGetSymbolAddress((void**)&p_u, g_u);
    cudaGetSymbolAddress((void**)&p_xdbl, g_xdbl);
    cudaGetSymbolAddress((void**)&p_xp, g_xp);
    cudaGetSymbolAddress((void**)&p_delta, g_delta);
    cudaGetSymbolAddress((void**)&p_xm2, g_xm2);
    cudaGetSymbolAddress((void**)&p_xm2n, g_xm2n);
    cudaGetSymbolAddress((void**)&p_y2, g_y2);
    cudaGetSymbolAddress((void**)&p_Hc, g_Hc);
    cudaGetSymbolAddress((void**)&p_Wc, g_Wc);
    cudaGetSymbolAddress((void**)&p_te, g_top_e);
    cudaGetSymbolAddress((void**)&p_tv, g_top_v);
    cudaGetSymbolAddress((void**)&p_off, g_off);
    cudaGetSymbolAddress((void**)&p_ptok, g_ptok);
    cudaGetSymbolAddress((void**)&p_pw, g_pw);
    cudaGetSymbolAddress((void**)&p_tp, g_tok_pair);

    __half *xnh, *xdh, *yh, *x2h, *hh, *wih, *wdh, *woh;
    cudaGetSymbolAddress((void**)&xnh, h_xn);
    cudaGetSymbolAddress((void**)&xdh, h_xd);
    cudaGetSymbolAddress((void**)&yh,  h_y);
    cudaGetSymbolAddress((void**)&x2h, h_x2);
    cudaGetSymbolAddress((void**)&hh,  h_h);
    cudaGetSymbolAddress((void**)&wih, h_wi);
    cudaGetSymbolAddress((void**)&wdh, h_wd);
    cudaGetSymbolAddress((void**)&woh, h_wo);

    const int SMEM = NSTG * STG_B;   // 48 KB
    cudaFuncSetAttribute((const void*)hgemm<0, 0, 0>, cudaFuncAttributeMaxDynamicSharedMemorySize, SMEM);
    cudaFuncSetAttribute((const void*)hgemm<3, 0, 0>, cudaFuncAttributeMaxDynamicSharedMemorySize, SMEM);
    cudaFuncSetAttribute((const void*)hgemm<2, 0, 0>, cudaFuncAttributeMaxDynamicSharedMemorySize, SMEM);
    cudaFuncSetAttribute((const void*)hgemm<1, 1, 1>, cudaFuncAttributeMaxDynamicSharedMemorySize, SMEM);
    cudaFuncSetAttribute((const void*)hgemm<0, 2, 1>, cudaFuncAttributeMaxDynamicSharedMemorySize, SMEM);

    // 0. convert small weights to fp16 in one fused launch (w1/w2 converted in-GEMM)
    conv_h3<<<1184, 256>>>((const float4*)in_proj_w, (uint2*)wih, 2 * DINNER * DMODEL / 4,
                           (const float4*)dt_proj_w, (uint2*)wdh, DINNER * DTRANK / 4,
                           (const float4*)out_proj_w, (uint2*)woh, DMODEL * DINNER / 4);

    // 1. xn = rmsnorm(x)
    rmsnorm_h<<<LSEQ, 256>>>(x, p_xn, xnh);
    // 2. xr = xn @ in_proj^T
    hgemm<0, 0, 0><<<dim3(16, 32), 256, SMEM>>>(xnh, DMODEL, wih, nullptr, DMODEL,
                                                p_xr, 2 * DINNER, LSEQ, 2 * DINNER,
                                                nullptr, nullptr, 0, nullptr, nullptr, nullptr);
    // 3. conv + silu (8 timesteps per thread)
    conv_silu<<<(LSEQ / 8) * DINNER / 256, 256>>>(p_xr, conv_w, conv_b, p_u);
    // 4. x_dbl = u @ x_proj^T (split-K exact fp32)
    gemm_sk<<<dim3(32, 2, SPLITK), 256>>>(p_u, DINNER, x_proj_w, DINNER,
                                          p_xp, XDBL, LSEQ, XDBL, DINNER / SPLITK);
    reduce_sk<<<(LSEQ * XDBL + 255) / 256, 256>>>(p_xp, p_xdbl, xdh, LSEQ * XDBL);
    // 5. delta = softplus(dt @ dt_proj^T + b)
    hgemm<3, 0, 0><<<dim3(16, 16), 256, SMEM>>>(xdh, XDBL, wdh, nullptr, DTRANK,
                                                p_delta, DINNER, LSEQ, DINNER,
                                                dt_proj_b, nullptr, 0, nullptr, nullptr, nullptr);
    // 6. chunked selective scan -> y fp16 (2 kernels; fix-up folded into final)
    scan_part<<<dim3(DINNER / 8, NCHUNK), 128>>>(p_delta, p_u, p_xdbl, A_log, p_Hc, p_Wc);
    scan_final<<<dim3(DINNER / 8, NCHUNK), 128>>>(p_delta, p_u, p_xdbl, A_log, Dvec,
                                                  p_xr, p_Hc, p_Wc, yh);
    // 7. xm2 = y @ out_proj^T + xn
    hgemm<2, 0, 0><<<dim3(16, 8), 256, SMEM>>>(yh, DINNER, woh, nullptr, DINNER,
                                               p_xm2, DMODEL, LSEQ, DMODEL,
                                               nullptr, p_xn, DMODEL, nullptr, nullptr, nullptr);
    // 8. xm2n = rmsnorm(xm2)
    rmsnorm_h<<<LSEQ, 256>>>(p_xm2, p_xm2n, x2h);
    // 9. gating + routing (fused)
    gate_topk<<<LSEQ / 4, 128>>>(p_xm2n, gate_w, p_te, p_tv);
    route_all<<<1, 256>>>(p_te, p_tv, p_off, p_ptok, p_pw, p_tp);
    // 10. expert GEMMs (fp32 weights, converted in-kernel)
    hgemm<1, 1, 1><<<dim3(32, 32, NEXP), 256, SMEM>>>(x2h, DMODEL, nullptr, w1, DMODEL,
                                                      nullptr, HIDDEN, 0, HIDDEN,
                                                      nullptr, nullptr, 0, p_off, p_ptok, hh);
    hgemm<0, 2, 1><<<dim3(32, 8, NEXP), 256, SMEM>>>(hh, HIDDEN, nullptr, w2, HIDDEN,
                                                     p_y2, DMODEL, 0, DMODEL,
                                                     nullptr, nullptr, 0, p_off, nullptr, nullptr);
    moe_combine<<<(LSEQ * DMODEL) / 256, 256>>>(x, p_y2, p_tp, p_pw, out);
}